// round 3
// baseline (speedup 1.0000x reference)
#include <cuda_runtime.h>
#include <cuda_bf16.h>
#include <cstddef>

// Problem constants
#define BB 256
#define SS 16
#define HH 8
#define HSZ 128
#define DD 1024
#define MM 1024
#define ROWS_L (BB*SS)        // 4096
#define N_ELEM ((size_t)ROWS_L*MM)   // 4,194,304

// ---------------- scratch (no allocations allowed) ----------------
__device__ float g_dense[BB*MM];        // inputs @ W_emb + b_emb
__device__ float g_xf[BB*MM];
__device__ float g_xi[BB*MM];
__device__ float g_xo[BB*MM];
__device__ float g_mp[ROWS_L*MM];       // m_state + attended
__device__ float g_mp2[ROWS_L*MM];      // (mp @ W_g + b_g) + mp
__device__ float g_gf[ROWS_L*MM];
__device__ float g_gi[ROWS_L*MM];
__device__ float g_go[ROWS_L*MM];

// ---------------- SGEMM: 128x128 block tile, BK=16, 8x8 per thread ----------
// MODE 0: C = A@B (+ bias if bias != nullptr)
// MODE 1: C = A@B + bias + extra[row, col]            (residual)
// MODE 2: C = A@B + bias + extra[row>>4, col]         (x broadcast over S)
template <int MODE>
__global__ void __launch_bounds__(256) sgemm128(
    const float* __restrict__ A, const float* __restrict__ B,
    const float* __restrict__ bias, const float* __restrict__ extra,
    float* __restrict__ C, int M, int N, int K)
{
    __shared__ float As[16][132];   // transposed A tile, padded
    __shared__ float Bs[16][128];

    const int tid = threadIdx.x;
    const int tx = tid & 15;        // 0..15 (col group)
    const int ty = tid >> 4;        // 0..15 (row group)

    const int bx = blockIdx.x;      // N tile
    const int by = blockIdx.y;      // M tile

    const float* Ablk = A + (size_t)by * 128 * K;
    const float* Bblk = B + bx * 128;

    // A tile load mapping: each thread 2 x float4
    const int a_row = tid >> 2;         // 0..63
    const int a_col = (tid & 3) * 4;    // 0,4,8,12
    // B tile load mapping: each thread 2 x float4
    const int b_k = tid >> 5;           // 0..7
    const int b_n = (tid & 31) * 4;     // 0..124

    float acc[8][8];
#pragma unroll
    for (int i = 0; i < 8; i++)
#pragma unroll
        for (int j = 0; j < 8; j++) acc[i][j] = 0.f;

    float ar[8], br[8];

    for (int k0 = 0; k0 < K; k0 += 16) {
        float4 a0 = *(const float4*)(Ablk + (size_t)a_row * K + k0 + a_col);
        float4 a1 = *(const float4*)(Ablk + (size_t)(a_row + 64) * K + k0 + a_col);
        float4 b0 = *(const float4*)(Bblk + (size_t)(k0 + b_k) * N + b_n);
        float4 b1 = *(const float4*)(Bblk + (size_t)(k0 + b_k + 8) * N + b_n);

        __syncthreads();   // previous tile's compute done before overwrite
        As[a_col + 0][a_row] = a0.x; As[a_col + 1][a_row] = a0.y;
        As[a_col + 2][a_row] = a0.z; As[a_col + 3][a_row] = a0.w;
        As[a_col + 0][a_row + 64] = a1.x; As[a_col + 1][a_row + 64] = a1.y;
        As[a_col + 2][a_row + 64] = a1.z; As[a_col + 3][a_row + 64] = a1.w;
        *(float4*)&Bs[b_k][b_n]     = b0;
        *(float4*)&Bs[b_k + 8][b_n] = b1;
        __syncthreads();

#pragma unroll
        for (int kk = 0; kk < 16; kk++) {
            *(float4*)&ar[0] = *(const float4*)&As[kk][ty * 8];
            *(float4*)&ar[4] = *(const float4*)&As[kk][ty * 8 + 4];
            *(float4*)&br[0] = *(const float4*)&Bs[kk][tx * 8];
            *(float4*)&br[4] = *(const float4*)&Bs[kk][tx * 8 + 4];
#pragma unroll
            for (int i = 0; i < 8; i++)
#pragma unroll
                for (int j = 0; j < 8; j++)
                    acc[i][j] += ar[i] * br[j];
        }
    }

    const int row0 = by * 128 + ty * 8;
    const int col0 = bx * 128 + tx * 8;

    float bcol[8];
#pragma unroll
    for (int j = 0; j < 8; j++)
        bcol[j] = (MODE >= 1 || bias != nullptr) ? bias[col0 + j] : 0.f;

#pragma unroll
    for (int i = 0; i < 8; i++) {
        const size_t r = row0 + i;
        float* crow = C + r * N + col0;
        const float* erow = nullptr;
        if (MODE == 1) erow = extra + r * N + col0;
        if (MODE == 2) erow = extra + (r >> 4) * N + col0;
#pragma unroll
        for (int j = 0; j < 8; j++) {
            float v = acc[i][j] + bcol[j];
            if (MODE >= 1) v += erow[j];
            crow[j] = v;
        }
    }
}

// ---------------- attention kernel: one block per (b,h) ----------------
// q = m_state[b,:,h,:]  (16x128); k=v=kv = [m_state rows ; dense row] (17x128)
// writes g_mp = m_state + attended
__global__ void __launch_bounds__(256) attn_kernel(
    const float* __restrict__ m_state, float* __restrict__ mp_out)
{
    const int bh = blockIdx.x;
    const int b = bh >> 3;
    const int h = bh & 7;
    const int tid = threadIdx.x;

    __shared__ float kv[17][128];
    __shared__ float sc[16][18];

    const float* mbase = m_state + (size_t)b * SS * MM + h * HSZ;
    for (int idx = tid; idx < 16 * 128; idx += 256) {
        int j = idx >> 7, d = idx & 127;
        kv[j][d] = mbase[(size_t)j * MM + d];
    }
    if (tid < 128) kv[16][tid] = g_dense[(size_t)b * MM + h * HSZ + tid];
    __syncthreads();

    // 272 dot products of length 128, warp-per-dot
    const int warp = tid >> 5, lane = tid & 31;
    for (int s = warp; s < 16 * 17; s += 8) {
        const int i = s / 17, j = s % 17;
        float sum = 0.f;
#pragma unroll
        for (int t = 0; t < 4; t++)
            sum += kv[i][lane + t * 32] * kv[j][lane + t * 32];
#pragma unroll
        for (int off = 16; off; off >>= 1)
            sum += __shfl_xor_sync(0xffffffff, sum, off);
        if (lane == 0) sc[i][j] = sum * 0.08838834764831845f; // 1/sqrt(128)
    }
    __syncthreads();

    // softmax over 17 keys, one thread per query row
    if (tid < 16) {
        float mx = -1e30f;
#pragma unroll
        for (int j = 0; j < 17; j++) mx = fmaxf(mx, sc[tid][j]);
        float sum = 0.f;
#pragma unroll
        for (int j = 0; j < 17; j++) {
            float e = expf(sc[tid][j] - mx);
            sc[tid][j] = e;
            sum += e;
        }
        const float inv = 1.f / sum;
#pragma unroll
        for (int j = 0; j < 17; j++) sc[tid][j] *= inv;
    }
    __syncthreads();

    // attended + residual
    for (int idx = tid; idx < 16 * 128; idx += 256) {
        const int i = idx >> 7, d = idx & 127;
        float a = 0.f;
#pragma unroll
        for (int j = 0; j < 17; j++) a += sc[i][j] * kv[j][d];
        mp_out[((size_t)b * SS + i) * MM + h * HSZ + d] = kv[i][d] + a;
    }
}

// ---------------- final elementwise gating ----------------
__device__ __forceinline__ float sigm(float x) { return 1.f / (1.f + expf(-x)); }

__global__ void __launch_bounds__(256) final_kernel(
    const float4* __restrict__ m, const float4* __restrict__ mp2,
    const float4* __restrict__ gf, const float4* __restrict__ gi,
    const float4* __restrict__ go, float4* __restrict__ out)
{
    const size_t i = (size_t)blockIdx.x * 256 + threadIdx.x; // 0 .. 1048575
    float4 mv = m[i], p = mp2[i], f = gf[i], ig = gi[i], og = go[i];
    float4 nm, nh;

    nm.x = sigm(mv.x * sigm(f.x) + 1.f) + p.x * sigm(sigm(ig.x));
    nm.y = sigm(mv.y * sigm(f.y) + 1.f) + p.y * sigm(sigm(ig.y));
    nm.z = sigm(mv.z * sigm(f.z) + 1.f) + p.z * sigm(sigm(ig.z));
    nm.w = sigm(mv.w * sigm(f.w) + 1.f) + p.w * sigm(sigm(ig.w));

    nh.x = tanhf(mv.x) * sigm(sigm(og.x));
    nh.y = tanhf(mv.y) * sigm(sigm(og.y));
    nh.z = tanhf(mv.z) * sigm(sigm(og.z));
    nh.w = tanhf(mv.w) * sigm(sigm(og.w));

    out[i] = nm;
    out[(N_ELEM / 4) + i] = nh;
}

// ---------------- launch ----------------
extern "C" void kernel_launch(void* const* d_in, const int* in_sizes, int n_in,
                              void* d_out, int out_size)
{
    const float* inputs  = (const float*)d_in[0];
    const float* h_state = (const float*)d_in[1];
    const float* m_state = (const float*)d_in[2];
    const float* W_emb   = (const float*)d_in[3];
    const float* b_emb   = (const float*)d_in[4];
    const float* W_g     = (const float*)d_in[5];
    const float* b_g     = (const float*)d_in[6];
    const float* W_wf    = (const float*)d_in[7];
    const float* W_wi    = (const float*)d_in[8];
    const float* W_wo    = (const float*)d_in[9];
    const float* W_uf    = (const float*)d_in[10];
    const float* b_uf    = (const float*)d_in[11];
    const float* W_ui    = (const float*)d_in[12];
    const float* b_ui    = (const float*)d_in[13];
    const float* W_uo    = (const float*)d_in[14];
    const float* b_uo    = (const float*)d_in[15];

    float *p_dense, *p_xf, *p_xi, *p_xo, *p_mp, *p_mp2, *p_gf, *p_gi, *p_go;
    cudaGetSymbolAddress((void**)&p_dense, g_dense);
    cudaGetSymbolAddress((void**)&p_xf, g_xf);
    cudaGetSymbolAddress((void**)&p_xi, g_xi);
    cudaGetSymbolAddress((void**)&p_xo, g_xo);
    cudaGetSymbolAddress((void**)&p_mp, g_mp);
    cudaGetSymbolAddress((void**)&p_mp2, g_mp2);
    cudaGetSymbolAddress((void**)&p_gf, g_gf);
    cudaGetSymbolAddress((void**)&p_gi, g_gi);
    cudaGetSymbolAddress((void**)&p_go, g_go);

    dim3 gS(MM / 128, BB / 128);      // (8, 2)
    dim3 gL(MM / 128, ROWS_L / 128);  // (8, 32)

    // input-side projections
    sgemm128<0><<<gS, 256>>>(inputs, W_emb, b_emb, nullptr, p_dense, BB, MM, DD);
    sgemm128<0><<<gS, 256>>>(inputs, W_wf, nullptr, nullptr, p_xf, BB, MM, DD);
    sgemm128<0><<<gS, 256>>>(inputs, W_wi, nullptr, nullptr, p_xi, BB, MM, DD);
    sgemm128<0><<<gS, 256>>>(inputs, W_wo, nullptr, nullptr, p_xo, BB, MM, DD);

    // attention -> memory proposal (pre W_g)
    attn_kernel<<<BB * HH, 256>>>(m_state, p_mp);

    // mp2 = mp @ W_g + b_g + mp
    sgemm128<1><<<gL, 256>>>(p_mp, W_g, b_g, p_mp, p_mp2, ROWS_L, MM, MM);

    // gate pre-activations: h_state @ W_u* + b_u* + x*[b]
    sgemm128<2><<<gL, 256>>>(h_state, W_uf, b_uf, p_xf, p_gf, ROWS_L, MM, MM);
    sgemm128<2><<<gL, 256>>>(h_state, W_ui, b_ui, p_xi, p_gi, ROWS_L, MM, MM);
    sgemm128<2><<<gL, 256>>>(h_state, W_uo, b_uo, p_xo, p_go, ROWS_L, MM, MM);

    // final gating -> [new_memories ; new_hidden]
    final_kernel<<<(unsigned)(N_ELEM / 4 / 256), 256>>>(
        (const float4*)m_state, (const float4*)p_mp2,
        (const float4*)p_gf, (const float4*)p_gi, (const float4*)p_go,
        (float4*)d_out);
}

// round 4
// speedup vs baseline: 2.5307x; 2.5307x over previous
#include <cuda_runtime.h>
#include <cuda_bf16.h>
#include <cstdint>
#include <cstddef>

// Problem constants
#define BB 256
#define SS 16
#define HH 8
#define HSZ 128
#define DD 1024
#define MM 1024
#define ROWS_L (BB*SS)               // 4096
#define N_ELEM ((size_t)ROWS_L*MM)   // 4,194,304

// ---------------- scratch ----------------
__device__ float g_dense[BB*MM];
__device__ float g_xf[BB*MM];
__device__ float g_xi[BB*MM];
__device__ float g_xo[BB*MM];
__device__ float g_mp[ROWS_L*MM];
__device__ float g_mp2[ROWS_L*MM];
__device__ float g_gf[ROWS_L*MM];
__device__ float g_gi[ROWS_L*MM];
__device__ float g_go[ROWS_L*MM];

// batched operand set, selected by blockIdx.z
struct GemmBatch {
    const float* B[4];
    const float* bias[4];
    const float* extra[4];
    float*       C[4];
};

__device__ __forceinline__ uint32_t f2tf(float x) {
    uint32_t r;
    asm("cvt.rna.tf32.f32 %0, %1;" : "=r"(r) : "f"(x));
    return r;
}

__device__ __forceinline__ void mma_tf32(
    float& d0, float& d1, float& d2, float& d3,
    uint32_t a0, uint32_t a1, uint32_t a2, uint32_t a3,
    uint32_t b0, uint32_t b1)
{
    asm volatile(
        "mma.sync.aligned.m16n8k8.row.col.f32.tf32.tf32.f32 "
        "{%0,%1,%2,%3}, {%4,%5,%6,%7}, {%8,%9}, {%0,%1,%2,%3};\n"
        : "+f"(d0), "+f"(d1), "+f"(d2), "+f"(d3)
        : "r"(a0), "r"(a1), "r"(a2), "r"(a3), "r"(b0), "r"(b1));
}

// ---------------- TF32 tensor-core GEMM ----------------
// C[128x128 tile] = A @ B (+bias) (+extra per MODE), batched over blockIdx.z
// MODE 0: +bias if non-null
// MODE 1: +bias +extra[row, col]
// MODE 2: +bias +extra[row>>4, col]
#define BK 16
#define LDT 132        // 128 + 4 pad (conflict-free frag reads)

template <int MODE>
__global__ void __launch_bounds__(256, 2) tf32gemm(
    const float* __restrict__ A, GemmBatch gb, int M, int N, int K)
{
    __shared__ uint32_t As[2][BK][LDT];   // [k][m] (transposed)
    __shared__ uint32_t Bs[2][BK][LDT];   // [k][n]

    const int z    = blockIdx.z;
    const int tid  = threadIdx.x;
    const int warp = tid >> 5, lane = tid & 31;
    const int gid  = lane >> 2, tig = lane & 3;
    const int warpM = (warp >> 1) * 32;   // 4 warps along M
    const int warpN = (warp & 1) * 64;    // 2 warps along N
    const int bx = blockIdx.x, by = blockIdx.y;

    const float* __restrict__ Ablk = A + (size_t)by * 128 * K;
    const float* __restrict__ Bblk = gb.B[z] + bx * 128;

    // A staging: thread -> row=tid>>1 (0..127), col base=(tid&1)*8
    const int ar = tid >> 1, ac = (tid & 1) * 8;
    // B staging: thread -> krow=tid>>4 (0..15), col=(tid&15)*8
    const int brk = tid >> 4, bcn = (tid & 15) * 8;

    float4 a0s, a1s, b0s, b1s;

    float acc[2][8][4];
#pragma unroll
    for (int i = 0; i < 2; i++)
#pragma unroll
        for (int j = 0; j < 8; j++)
#pragma unroll
            for (int q = 0; q < 4; q++) acc[i][j][q] = 0.f;

    // prologue: load + convert + store tile 0
    {
        a0s = *(const float4*)(Ablk + (size_t)ar * K + ac);
        a1s = *(const float4*)(Ablk + (size_t)ar * K + ac + 4);
        b0s = *(const float4*)(Bblk + (size_t)brk * N + bcn);
        b1s = *(const float4*)(Bblk + (size_t)brk * N + bcn + 4);
        As[0][ac+0][ar] = f2tf(a0s.x); As[0][ac+1][ar] = f2tf(a0s.y);
        As[0][ac+2][ar] = f2tf(a0s.z); As[0][ac+3][ar] = f2tf(a0s.w);
        As[0][ac+4][ar] = f2tf(a1s.x); As[0][ac+5][ar] = f2tf(a1s.y);
        As[0][ac+6][ar] = f2tf(a1s.z); As[0][ac+7][ar] = f2tf(a1s.w);
        uint4 t0 = { f2tf(b0s.x), f2tf(b0s.y), f2tf(b0s.z), f2tf(b0s.w) };
        uint4 t1 = { f2tf(b1s.x), f2tf(b1s.y), f2tf(b1s.z), f2tf(b1s.w) };
        *(uint4*)&Bs[0][brk][bcn]     = t0;
        *(uint4*)&Bs[0][brk][bcn + 4] = t1;
    }
    __syncthreads();

    const int nt = K / BK;   // 64
    for (int t = 0; t < nt; t++) {
        const int buf = t & 1;
        if (t + 1 < nt) {
            const int k0 = (t + 1) * BK;
            a0s = *(const float4*)(Ablk + (size_t)ar * K + k0 + ac);
            a1s = *(const float4*)(Ablk + (size_t)ar * K + k0 + ac + 4);
            b0s = *(const float4*)(Bblk + (size_t)(k0 + brk) * N + bcn);
            b1s = *(const float4*)(Bblk + (size_t)(k0 + brk) * N + bcn + 4);
        }

        // compute on smem[buf]: 2 k-steps of 8
#pragma unroll
        for (int ks = 0; ks < BK; ks += 8) {
            uint32_t afr[2][4], bfr[8][2];
#pragma unroll
            for (int mf = 0; mf < 2; mf++) {
                const int m0 = warpM + mf * 16 + gid;
                afr[mf][0] = As[buf][ks + tig    ][m0];
                afr[mf][1] = As[buf][ks + tig    ][m0 + 8];
                afr[mf][2] = As[buf][ks + tig + 4][m0];
                afr[mf][3] = As[buf][ks + tig + 4][m0 + 8];
            }
#pragma unroll
            for (int nf = 0; nf < 8; nf++) {
                const int n0 = warpN + nf * 8 + gid;
                bfr[nf][0] = Bs[buf][ks + tig    ][n0];
                bfr[nf][1] = Bs[buf][ks + tig + 4][n0];
            }
#pragma unroll
            for (int mf = 0; mf < 2; mf++)
#pragma unroll
                for (int nf = 0; nf < 8; nf++)
                    mma_tf32(acc[mf][nf][0], acc[mf][nf][1],
                             acc[mf][nf][2], acc[mf][nf][3],
                             afr[mf][0], afr[mf][1], afr[mf][2], afr[mf][3],
                             bfr[nf][0], bfr[nf][1]);
        }

        if (t + 1 < nt) {
            const int nb = buf ^ 1;
            As[nb][ac+0][ar] = f2tf(a0s.x); As[nb][ac+1][ar] = f2tf(a0s.y);
            As[nb][ac+2][ar] = f2tf(a0s.z); As[nb][ac+3][ar] = f2tf(a0s.w);
            As[nb][ac+4][ar] = f2tf(a1s.x); As[nb][ac+5][ar] = f2tf(a1s.y);
            As[nb][ac+6][ar] = f2tf(a1s.z); As[nb][ac+7][ar] = f2tf(a1s.w);
            uint4 t0 = { f2tf(b0s.x), f2tf(b0s.y), f2tf(b0s.z), f2tf(b0s.w) };
            uint4 t1 = { f2tf(b1s.x), f2tf(b1s.y), f2tf(b1s.z), f2tf(b1s.w) };
            *(uint4*)&Bs[nb][brk][bcn]     = t0;
            *(uint4*)&Bs[nb][brk][bcn + 4] = t1;
        }
        __syncthreads();
    }

    // epilogue
    const float* __restrict__ bias  = gb.bias[z];
    const float* __restrict__ extra = gb.extra[z];
    float* __restrict__ C           = gb.C[z];
    const int row0 = by * 128 + warpM;
    const int col0 = bx * 128 + warpN;

#pragma unroll
    for (int mf = 0; mf < 2; mf++) {
#pragma unroll
        for (int nf = 0; nf < 8; nf++) {
            const int c = col0 + nf * 8 + 2 * tig;
            float bv0 = 0.f, bv1 = 0.f;
            if (bias) { bv0 = bias[c]; bv1 = bias[c + 1]; }
#pragma unroll
            for (int half = 0; half < 2; half++) {
                const int r = row0 + mf * 16 + gid + half * 8;
                float v0 = acc[mf][nf][half * 2 + 0] + bv0;
                float v1 = acc[mf][nf][half * 2 + 1] + bv1;
                if (MODE == 1) {
                    const float2 e = *(const float2*)(extra + (size_t)r * N + c);
                    v0 += e.x; v1 += e.y;
                } else if (MODE == 2) {
                    const float2 e = *(const float2*)(extra + (size_t)(r >> 4) * N + c);
                    v0 += e.x; v1 += e.y;
                }
                float2 out = { v0, v1 };
                *(float2*)(C + (size_t)r * N + c) = out;
            }
        }
    }
}

// ---------------- attention kernel (unchanged, correct) ----------------
__global__ void __launch_bounds__(256) attn_kernel(
    const float* __restrict__ m_state, float* __restrict__ mp_out)
{
    const int bh = blockIdx.x;
    const int b = bh >> 3;
    const int h = bh & 7;
    const int tid = threadIdx.x;

    __shared__ float kv[17][128];
    __shared__ float sc[16][18];

    const float* mbase = m_state + (size_t)b * SS * MM + h * HSZ;
    for (int idx = tid; idx < 16 * 128; idx += 256) {
        int j = idx >> 7, d = idx & 127;
        kv[j][d] = mbase[(size_t)j * MM + d];
    }
    if (tid < 128) kv[16][tid] = g_dense[(size_t)b * MM + h * HSZ + tid];
    __syncthreads();

    const int warp = tid >> 5, lane = tid & 31;
    for (int s = warp; s < 16 * 17; s += 8) {
        const int i = s / 17, j = s % 17;
        float sum = 0.f;
#pragma unroll
        for (int t = 0; t < 4; t++)
            sum += kv[i][lane + t * 32] * kv[j][lane + t * 32];
#pragma unroll
        for (int off = 16; off; off >>= 1)
            sum += __shfl_xor_sync(0xffffffff, sum, off);
        if (lane == 0) sc[i][j] = sum * 0.08838834764831845f;
    }
    __syncthreads();

    if (tid < 16) {
        float mx = -1e30f;
#pragma unroll
        for (int j = 0; j < 17; j++) mx = fmaxf(mx, sc[tid][j]);
        float sum = 0.f;
#pragma unroll
        for (int j = 0; j < 17; j++) {
            float e = expf(sc[tid][j] - mx);
            sc[tid][j] = e;
            sum += e;
        }
        const float inv = 1.f / sum;
#pragma unroll
        for (int j = 0; j < 17; j++) sc[tid][j] *= inv;
    }
    __syncthreads();

    for (int idx = tid; idx < 16 * 128; idx += 256) {
        const int i = idx >> 7, d = idx & 127;
        float a = 0.f;
#pragma unroll
        for (int j = 0; j < 17; j++) a += sc[i][j] * kv[j][d];
        mp_out[((size_t)b * SS + i) * MM + h * HSZ + d] = kv[i][d] + a;
    }
}

// ---------------- final elementwise gating ----------------
__device__ __forceinline__ float sigm(float x) { return 1.f / (1.f + expf(-x)); }

__global__ void __launch_bounds__(256) final_kernel(
    const float4* __restrict__ m, const float4* __restrict__ mp2,
    const float4* __restrict__ gf, const float4* __restrict__ gi,
    const float4* __restrict__ go, float4* __restrict__ out)
{
    const size_t i = (size_t)blockIdx.x * 256 + threadIdx.x;
    float4 mv = m[i], p = mp2[i], f = gf[i], ig = gi[i], og = go[i];
    float4 nm, nh;

    nm.x = sigm(mv.x * sigm(f.x) + 1.f) + p.x * sigm(sigm(ig.x));
    nm.y = sigm(mv.y * sigm(f.y) + 1.f) + p.y * sigm(sigm(ig.y));
    nm.z = sigm(mv.z * sigm(f.z) + 1.f) + p.z * sigm(sigm(ig.z));
    nm.w = sigm(mv.w * sigm(f.w) + 1.f) + p.w * sigm(sigm(ig.w));

    nh.x = tanhf(mv.x) * sigm(sigm(og.x));
    nh.y = tanhf(mv.y) * sigm(sigm(og.y));
    nh.z = tanhf(mv.z) * sigm(sigm(og.z));
    nh.w = tanhf(mv.w) * sigm(sigm(og.w));

    out[i] = nm;
    out[(N_ELEM / 4) + i] = nh;
}

// ---------------- launch ----------------
extern "C" void kernel_launch(void* const* d_in, const int* in_sizes, int n_in,
                              void* d_out, int out_size)
{
    const float* inputs  = (const float*)d_in[0];
    const float* h_state = (const float*)d_in[1];
    const float* m_state = (const float*)d_in[2];
    const float* W_emb   = (const float*)d_in[3];
    const float* b_emb   = (const float*)d_in[4];
    const float* W_g     = (const float*)d_in[5];
    const float* b_g     = (const float*)d_in[6];
    const float* W_wf    = (const float*)d_in[7];
    const float* W_wi    = (const float*)d_in[8];
    const float* W_wo    = (const float*)d_in[9];
    const float* W_uf    = (const float*)d_in[10];
    const float* b_uf    = (const float*)d_in[11];
    const float* W_ui    = (const float*)d_in[12];
    const float* b_ui    = (const float*)d_in[13];
    const float* W_uo    = (const float*)d_in[14];
    const float* b_uo    = (const float*)d_in[15];

    float *p_dense, *p_xf, *p_xi, *p_xo, *p_mp, *p_mp2, *p_gf, *p_gi, *p_go;
    cudaGetSymbolAddress((void**)&p_dense, g_dense);
    cudaGetSymbolAddress((void**)&p_xf, g_xf);
    cudaGetSymbolAddress((void**)&p_xi, g_xi);
    cudaGetSymbolAddress((void**)&p_xo, g_xo);
    cudaGetSymbolAddress((void**)&p_mp, g_mp);
    cudaGetSymbolAddress((void**)&p_mp2, g_mp2);
    cudaGetSymbolAddress((void**)&p_gf, g_gf);
    cudaGetSymbolAddress((void**)&p_gi, g_gi);
    cudaGetSymbolAddress((void**)&p_go, g_go);

    // 1) 4 input projections in one launch (z = emb, wf, wi, wo)
    {
        GemmBatch gb;
        gb.B[0] = W_emb; gb.B[1] = W_wf; gb.B[2] = W_wi; gb.B[3] = W_wo;
        gb.bias[0] = b_emb; gb.bias[1] = nullptr; gb.bias[2] = nullptr; gb.bias[3] = nullptr;
        gb.extra[0] = gb.extra[1] = gb.extra[2] = gb.extra[3] = nullptr;
        gb.C[0] = p_dense; gb.C[1] = p_xf; gb.C[2] = p_xi; gb.C[3] = p_xo;
        tf32gemm<0><<<dim3(MM/128, BB/128, 4), 256>>>(inputs, gb, BB, MM, DD);
    }

    // 2) attention -> memory proposal (needs g_dense)
    attn_kernel<<<BB * HH, 256>>>(m_state, p_mp);

    // 3) mp2 = mp @ W_g + b_g + mp
    {
        GemmBatch gb;
        gb.B[0] = W_g; gb.bias[0] = b_g; gb.extra[0] = p_mp; gb.C[0] = p_mp2;
        gb.B[1] = gb.B[2] = gb.B[3] = nullptr;
        gb.bias[1] = gb.bias[2] = gb.bias[3] = nullptr;
        gb.extra[1] = gb.extra[2] = gb.extra[3] = nullptr;
        gb.C[1] = gb.C[2] = gb.C[3] = nullptr;
        tf32gemm<1><<<dim3(MM/128, ROWS_L/128, 1), 256>>>(p_mp, gb, ROWS_L, MM, MM);
    }

    // 4) 3 gate pre-activations in one launch (z = f, i, o)
    {
        GemmBatch gb;
        gb.B[0] = W_uf; gb.B[1] = W_ui; gb.B[2] = W_uo; gb.B[3] = nullptr;
        gb.bias[0] = b_uf; gb.bias[1] = b_ui; gb.bias[2] = b_uo; gb.bias[3] = nullptr;
        gb.extra[0] = p_xf; gb.extra[1] = p_xi; gb.extra[2] = p_xo; gb.extra[3] = nullptr;
        gb.C[0] = p_gf; gb.C[1] = p_gi; gb.C[2] = p_go; gb.C[3] = nullptr;
        tf32gemm<2><<<dim3(MM/128, ROWS_L/128, 3), 256>>>(h_state, gb, ROWS_L, MM, MM);
    }

    // 5) final gating
    final_kernel<<<(unsigned)(N_ELEM / 4 / 256), 256>>>(
        (const float4*)m_state, (const float4*)p_mp2,
        (const float4*)p_gf, (const float4*)p_gi, (const float4*)p_go,
        (float4*)d_out);
}

// round 7
// speedup vs baseline: 3.0345x; 1.1991x over previous
#include <cuda_runtime.h>
#include <cuda_bf16.h>
#include <cstdint>
#include <cstddef>

// Problem constants
#define BB 256
#define SS 16
#define HH 8
#define HSZ 128
#define DD 1024
#define MM 1024
#define ROWS_L (BB*SS)               // 4096
#define N_ELEM ((size_t)ROWS_L*MM)   // 4,194,304

// ---------------- scratch ----------------
__device__ float g_dense[BB*MM];
__device__ float g_xf[BB*MM];
__device__ float g_xi[BB*MM];
__device__ float g_xo[BB*MM];
__device__ float g_mp[ROWS_L*MM];
__device__ float g_mp2[ROWS_L*MM];
__device__ float g_gf[ROWS_L*MM];
__device__ float g_gi[ROWS_L*MM];
__device__ float g_go[ROWS_L*MM];

struct GemmBatch {
    const float* B[4];
    const float* bias[4];
    const float* extra[4];
    float*       C[4];
};

__device__ __forceinline__ uint32_t smem_u32(const void* p) {
    return (uint32_t)__cvta_generic_to_shared(p);
}

__device__ __forceinline__ void ldsm4(uint32_t& r0, uint32_t& r1,
                                      uint32_t& r2, uint32_t& r3, uint32_t addr) {
    asm volatile("ldmatrix.sync.aligned.m8n8.x4.shared.b16 {%0,%1,%2,%3}, [%4];"
                 : "=r"(r0), "=r"(r1), "=r"(r2), "=r"(r3) : "r"(addr));
}

__device__ __forceinline__ void mma_tf32(
    float& d0, float& d1, float& d2, float& d3,
    uint32_t a0, uint32_t a1, uint32_t a2, uint32_t a3,
    uint32_t b0, uint32_t b1)
{
    asm volatile(
        "mma.sync.aligned.m16n8k8.row.col.f32.tf32.tf32.f32 "
        "{%0,%1,%2,%3}, {%4,%5,%6,%7}, {%8,%9}, {%0,%1,%2,%3};\n"
        : "+f"(d0), "+f"(d1), "+f"(d2), "+f"(d3)
        : "r"(a0), "r"(a1), "r"(a2), "r"(a3), "r"(b0), "r"(b1));
}

// ---------------- TF32 tensor-core GEMM with ldmatrix ----------------
// CTA tile 128x128, BK=16, 8 warps as 4(M)x2(N) -> warp tile 32x64.
// As: [m][k] m-major (LDT=20 pad). Bs: [n][k] transposed, chunk-swizzled.
#define BK 16
#define LDT 20                      // words per smem row (16 data + 4 pad)
#define TILE_WORDS (128 * LDT)      // per buffer
#define BUF_BYTES (TILE_WORDS * 4)

template <int MODE>
__global__ void __launch_bounds__(256, 2) tf32gemm(
    const float* __restrict__ A, GemmBatch gb, int M, int N, int K)
{
    __shared__ uint32_t As[2 * TILE_WORDS];
    __shared__ uint32_t Bs[2 * TILE_WORDS];

    const int z    = blockIdx.z;
    const int tid  = threadIdx.x;
    const int warp = tid >> 5, lane = tid & 31;
    const int tig  = lane & 3;
    const int gid  = lane >> 2;
    const int warpM = (warp >> 1) * 32;
    const int warpN = (warp & 1) * 64;
    const int bx = blockIdx.x, by = blockIdx.y;

    const float* __restrict__ Ablk = A + (size_t)by * 128 * K;
    const float* __restrict__ Bblk = gb.B[z] + bx * 128;

    // staging: A -> row ar (0..127), cols ac..ac+7 ; B -> k-row bk, cols bn..bn+7
    const int ar = tid >> 1, ac = (tid & 1) * 8;
    const int bk = tid >> 4, bn = (tid & 15) * 8;
    // B transpose-store column (constant per thread): chunk swizzled by (n>>3)&3
    const int bcol = (((bk >> 2) ^ ((tid & 15) & 3)) << 2) + (bk & 3);

    const uint32_t as_base = smem_u32(As);
    const uint32_t bs_base = smem_u32(Bs);

    // ldmatrix lane addressing
    // A: matrices {(m0:8,c0),(m8:16,c0),(m0:8,c0+1),(m8:16,c0+1)}
    const uint32_t aRow   = (lane & 7) + ((lane >> 3) & 1) * 8;   // + warpM + mf*16
    const uint32_t aChunk = (lane >> 4);                          // + ks/4
    uint32_t aW[2];
#pragma unroll
    for (int mf = 0; mf < 2; mf++)
        aW[mf] = (warpM + mf * 16 + aRow) * LDT + aChunk * 4;     // + ks words

    // B: matrices {(n0:8,c0),(n0:8,c0+1),(n8:16,c0),(n8:16,c0+1)}
    uint32_t bRowW[4], bKey[4];
    const uint32_t bcb = (lane >> 3) & 1;
#pragma unroll
    for (int p = 0; p < 4; p++) {
        uint32_t row = warpN + p * 16 + (lane & 7) + ((lane >> 4) & 1) * 8;
        bRowW[p] = row * LDT;
        bKey[p]  = (row >> 3) & 3;
    }

    float acc[2][8][4];
#pragma unroll
    for (int i = 0; i < 2; i++)
#pragma unroll
        for (int j = 0; j < 8; j++)
#pragma unroll
            for (int q = 0; q < 4; q++) acc[i][j][q] = 0.f;

    float4 a0s, a1s, b0s, b1s;

    // prologue: tile 0 -> buffer 0
    {
        a0s = *(const float4*)(Ablk + (size_t)ar * K + ac);
        a1s = *(const float4*)(Ablk + (size_t)ar * K + ac + 4);
        b0s = *(const float4*)(Bblk + (size_t)bk * N + bn);
        b1s = *(const float4*)(Bblk + (size_t)bk * N + bn + 4);
        *(float4*)&As[ar * LDT + ac]     = a0s;
        *(float4*)&As[ar * LDT + ac + 4] = a1s;
        const float bv[8] = { b0s.x, b0s.y, b0s.z, b0s.w, b1s.x, b1s.y, b1s.z, b1s.w };
#pragma unroll
        for (int j = 0; j < 8; j++)
            Bs[(bn + j) * LDT + bcol] = __float_as_uint(bv[j]);
    }
    __syncthreads();

    const int nt = K / BK;
    for (int t = 0; t < nt; t++) {
        const int buf = t & 1;
        if (t + 1 < nt) {
            const int k0 = (t + 1) * BK;
            a0s = *(const float4*)(Ablk + (size_t)ar * K + k0 + ac);
            a1s = *(const float4*)(Ablk + (size_t)ar * K + k0 + ac + 4);
            b0s = *(const float4*)(Bblk + (size_t)(k0 + bk) * N + bn);
            b1s = *(const float4*)(Bblk + (size_t)(k0 + bk) * N + bn + 4);
        }

        const uint32_t abuf = as_base + buf * BUF_BYTES;
        const uint32_t bbuf = bs_base + buf * BUF_BYTES;

#pragma unroll
        for (int ks = 0; ks < BK; ks += 8) {
            uint32_t afr[2][4], bfr[8][2];
#pragma unroll
            for (int mf = 0; mf < 2; mf++)
                ldsm4(afr[mf][0], afr[mf][1], afr[mf][2], afr[mf][3],
                      abuf + ((aW[mf] + ks) << 2));
            const uint32_t c0 = ks >> 2;
#pragma unroll
            for (int p = 0; p < 4; p++) {
                const uint32_t chunk = (c0 + bcb) ^ bKey[p];
                ldsm4(bfr[2*p][0], bfr[2*p][1], bfr[2*p+1][0], bfr[2*p+1][1],
                      bbuf + ((bRowW[p] + chunk * 4) << 2));
            }
#pragma unroll
            for (int mf = 0; mf < 2; mf++)
#pragma unroll
                for (int nf = 0; nf < 8; nf++)
                    mma_tf32(acc[mf][nf][0], acc[mf][nf][1],
                             acc[mf][nf][2], acc[mf][nf][3],
                             afr[mf][0], afr[mf][1], afr[mf][2], afr[mf][3],
                             bfr[nf][0], bfr[nf][1]);
        }

        if (t + 1 < nt) {
            uint32_t* Ad = &As[(buf ^ 1) * TILE_WORDS];
            uint32_t* Bd = &Bs[(buf ^ 1) * TILE_WORDS];
            *(float4*)&Ad[ar * LDT + ac]     = a0s;
            *(float4*)&Ad[ar * LDT + ac + 4] = a1s;
            const float bv[8] = { b0s.x, b0s.y, b0s.z, b0s.w, b1s.x, b1s.y, b1s.z, b1s.w };
#pragma unroll
            for (int j = 0; j < 8; j++)
                Bd[(bn + j) * LDT + bcol] = __float_as_uint(bv[j]);
        }
        __syncthreads();
    }

    // epilogue
    const float* __restrict__ bias  = gb.bias[z];
    const float* __restrict__ extra = gb.extra[z];
    float* __restrict__ C           = gb.C[z];
    const int row0 = by * 128 + warpM;
    const int col0 = bx * 128 + warpN;

#pragma unroll
    for (int mf = 0; mf < 2; mf++) {
#pragma unroll
        for (int nf = 0; nf < 8; nf++) {
            const int c = col0 + nf * 8 + 2 * tig;
            float bv0 = 0.f, bv1 = 0.f;
            if (bias) { bv0 = bias[c]; bv1 = bias[c + 1]; }
#pragma unroll
            for (int half = 0; half < 2; half++) {
                const int r = row0 + mf * 16 + gid + half * 8;
                float v0 = acc[mf][nf][half * 2 + 0] + bv0;
                float v1 = acc[mf][nf][half * 2 + 1] + bv1;
                if (MODE == 1) {
                    const float2 e = *(const float2*)(extra + (size_t)r * N + c);
                    v0 += e.x; v1 += e.y;
                } else if (MODE == 2) {
                    const float2 e = *(const float2*)(extra + (size_t)(r >> 4) * N + c);
                    v0 += e.x; v1 += e.y;
                }
                float2 out = { v0, v1 };
                *(float2*)(C + (size_t)r * N + c) = out;
            }
        }
    }
}

// ---------------- attention kernel ----------------
__global__ void __launch_bounds__(256) attn_kernel(
    const float* __restrict__ m_state, float* __restrict__ mp_out)
{
    const int bh = blockIdx.x;
    const int b = bh >> 3;
    const int h = bh & 7;
    const int tid = threadIdx.x;

    __shared__ float kv[17][128];
    __shared__ float sc[16][18];

    const float* mbase = m_state + (size_t)b * SS * MM + h * HSZ;
    for (int idx = tid; idx < 16 * 128; idx += 256) {
        int j = idx >> 7, d = idx & 127;
        kv[j][d] = mbase[(size_t)j * MM + d];
    }
    if (tid < 128) kv[16][tid] = g_dense[(size_t)b * MM + h * HSZ + tid];
    __syncthreads();

    const int warp = tid >> 5, lane = tid & 31;
    for (int s = warp; s < 16 * 17; s += 8) {
        const int i = s / 17, j = s % 17;
        float sum = 0.f;
#pragma unroll
        for (int t = 0; t < 4; t++)
            sum += kv[i][lane + t * 32] * kv[j][lane + t * 32];
#pragma unroll
        for (int off = 16; off; off >>= 1)
            sum += __shfl_xor_sync(0xffffffff, sum, off);
        if (lane == 0) sc[i][j] = sum * 0.08838834764831845f;
    }
    __syncthreads();

    if (tid < 16) {
        float mx = -1e30f;
#pragma unroll
        for (int j = 0; j < 17; j++) mx = fmaxf(mx, sc[tid][j]);
        float sum = 0.f;
#pragma unroll
        for (int j = 0; j < 17; j++) {
            float e = expf(sc[tid][j] - mx);
            sc[tid][j] = e;
            sum += e;
        }
        const float inv = 1.f / sum;
#pragma unroll
        for (int j = 0; j < 17; j++) sc[tid][j] *= inv;
    }
    __syncthreads();

    for (int idx = tid; idx < 16 * 128; idx += 256) {
        const int i = idx >> 7, d = idx & 127;
        float a = 0.f;
#pragma unroll
        for (int j = 0; j < 17; j++) a += sc[i][j] * kv[j][d];
        mp_out[((size_t)b * SS + i) * MM + h * HSZ + d] = kv[i][d] + a;
    }
}

// ---------------- final elementwise gating ----------------
__device__ __forceinline__ float sigm(float x) { return 1.f / (1.f + expf(-x)); }

__global__ void __launch_bounds__(256) final_kernel(
    const float4* __restrict__ m, const float4* __restrict__ mp2,
    const float4* __restrict__ gf, const float4* __restrict__ gi,
    const float4* __restrict__ go, float4* __restrict__ out)
{
    const size_t i = (size_t)blockIdx.x * 256 + threadIdx.x;
    float4 mv = m[i], p = mp2[i], f = gf[i], ig = gi[i], og = go[i];
    float4 nm, nh;

    nm.x = sigm(mv.x * sigm(f.x) + 1.f) + p.x * sigm(sigm(ig.x));
    nm.y = sigm(mv.y * sigm(f.y) + 1.f) + p.y * sigm(sigm(ig.y));
    nm.z = sigm(mv.z * sigm(f.z) + 1.f) + p.z * sigm(sigm(ig.z));
    nm.w = sigm(mv.w * sigm(f.w) + 1.f) + p.w * sigm(sigm(ig.w));

    nh.x = tanhf(mv.x) * sigm(sigm(og.x));
    nh.y = tanhf(mv.y) * sigm(sigm(og.y));
    nh.z = tanhf(mv.z) * sigm(sigm(og.z));
    nh.w = tanhf(mv.w) * sigm(sigm(og.w));

    out[i] = nm;
    out[(N_ELEM / 4) + i] = nh;
}

// ---------------- launch ----------------
extern "C" void kernel_launch(void* const* d_in, const int* in_sizes, int n_in,
                              void* d_out, int out_size)
{
    const float* inputs  = (const float*)d_in[0];
    const float* h_state = (const float*)d_in[1];
    const float* m_state = (const float*)d_in[2];
    const float* W_emb   = (const float*)d_in[3];
    const float* b_emb   = (const float*)d_in[4];
    const float* W_g     = (const float*)d_in[5];
    const float* b_g     = (const float*)d_in[6];
    const float* W_wf    = (const float*)d_in[7];
    const float* W_wi    = (const float*)d_in[8];
    const float* W_wo    = (const float*)d_in[9];
    const float* W_uf    = (const float*)d_in[10];
    const float* b_uf    = (const float*)d_in[11];
    const float* W_ui    = (const float*)d_in[12];
    const float* b_ui    = (const float*)d_in[13];
    const float* W_uo    = (const float*)d_in[14];
    const float* b_uo    = (const float*)d_in[15];

    float *p_dense, *p_xf, *p_xi, *p_xo, *p_mp, *p_mp2, *p_gf, *p_gi, *p_go;
    cudaGetSymbolAddress((void**)&p_dense, g_dense);
    cudaGetSymbolAddress((void**)&p_xf, g_xf);
    cudaGetSymbolAddress((void**)&p_xi, g_xi);
    cudaGetSymbolAddress((void**)&p_xo, g_xo);
    cudaGetSymbolAddress((void**)&p_mp, g_mp);
    cudaGetSymbolAddress((void**)&p_mp2, g_mp2);
    cudaGetSymbolAddress((void**)&p_gf, g_gf);
    cudaGetSymbolAddress((void**)&p_gi, g_gi);
    cudaGetSymbolAddress((void**)&p_go, g_go);

    // 1) 4 input projections in one launch
    {
        GemmBatch gb;
        gb.B[0] = W_emb; gb.B[1] = W_wf; gb.B[2] = W_wi; gb.B[3] = W_wo;
        gb.bias[0] = b_emb; gb.bias[1] = nullptr; gb.bias[2] = nullptr; gb.bias[3] = nullptr;
        gb.extra[0] = gb.extra[1] = gb.extra[2] = gb.extra[3] = nullptr;
        gb.C[0] = p_dense; gb.C[1] = p_xf; gb.C[2] = p_xi; gb.C[3] = p_xo;
        tf32gemm<0><<<dim3(MM/128, BB/128, 4), 256>>>(inputs, gb, BB, MM, DD);
    }

    // 2) attention -> memory proposal
    attn_kernel<<<BB * HH, 256>>>(m_state, p_mp);

    // 3) 3 gate pre-activations (independent of attention result)
    {
        GemmBatch gb;
        gb.B[0] = W_uf; gb.B[1] = W_ui; gb.B[2] = W_uo; gb.B[3] = nullptr;
        gb.bias[0] = b_uf; gb.bias[1] = b_ui; gb.bias[2] = b_uo; gb.bias[3] = nullptr;
        gb.extra[0] = p_xf; gb.extra[1] = p_xi; gb.extra[2] = p_xo; gb.extra[3] = nullptr;
        gb.C[0] = p_gf; gb.C[1] = p_gi; gb.C[2] = p_go; gb.C[3] = nullptr;
        tf32gemm<2><<<dim3(MM/128, ROWS_L/128, 3), 256>>>(h_state, gb, ROWS_L, MM, MM);
    }

    // 4) mp2 = mp @ W_g + b_g + mp
    {
        GemmBatch gb;
        gb.B[0] = W_g; gb.bias[0] = b_g; gb.extra[0] = p_mp; gb.C[0] = p_mp2;
        gb.B[1] = gb.B[2] = gb.B[3] = nullptr;
        gb.bias[1] = gb.bias[2] = gb.bias[3] = nullptr;
        gb.extra[1] = gb.extra[2] = gb.extra[3] = nullptr;
        gb.C[1] = gb.C[2] = gb.C[3] = nullptr;
        tf32gemm<1><<<dim3(MM/128, ROWS_L/128, 1), 256>>>(p_mp, gb, ROWS_L, MM, MM);
    }

    // 5) final gating
    final_kernel<<<(unsigned)(N_ELEM / 4 / 256), 256>>>(
        (const float4*)m_state, (const float4*)p_mp2,
        (const float4*)p_gf, (const float4*)p_gi, (const float4*)p_go,
        (float4*)d_out);
}

// round 9
// speedup vs baseline: 4.3100x; 1.4203x over previous
#include <cuda_runtime.h>
#include <cstdint>
#include <cstddef>

// Problem constants
#define BB 256
#define SS 16
#define HH 8
#define HSZ 128
#define DD 1024
#define MM 1024
#define ROWS_L (BB*SS)               // 4096
#define N_ELEM ((size_t)ROWS_L*MM)   // 4,194,304

// ---------------- scratch ----------------
__device__ float g_dense[BB*MM];
__device__ float g_xf[BB*MM];
__device__ float g_xi[BB*MM];
__device__ float g_xo[BB*MM];
__device__ float g_mp[ROWS_L*MM];
__device__ float g_mp2[ROWS_L*MM];
__device__ float g_gf[ROWS_L*MM];
__device__ float g_gi[ROWS_L*MM];
__device__ float g_go[ROWS_L*MM];
__device__ float g_wT[8][MM*MM];     // transposed weights [N][K]

struct GemmJob {
    const float* A;      // [Mrows, K] row-major (k-contiguous)
    const float* BT;     // [N, K] row-major (transposed weight, k-contiguous)
    const float* bias;   // [N] or null
    const float* extra;  // residual per mode
    float*       C;      // [Mrows, N]
    int mode;            // 0: none, 1: +extra[r][c], 2: +extra[r>>4][c]
};
struct GemmJobs { GemmJob j[4]; };
struct TPtrs { const float* src[8]; float* dst[8]; };

__device__ __forceinline__ uint32_t smem_u32(const void* p) {
    return (uint32_t)__cvta_generic_to_shared(p);
}
__device__ __forceinline__ void cp16(uint32_t dst, const void* src) {
    asm volatile("cp.async.cg.shared.global [%0], [%1], 16;" :: "r"(dst), "l"(src));
}
__device__ __forceinline__ void cp_commit() {
    asm volatile("cp.async.commit_group;" ::: "memory");
}
template <int N>
__device__ __forceinline__ void cp_wait() {
    asm volatile("cp.async.wait_group %0;" :: "n"(N) : "memory");
}
__device__ __forceinline__ void ldsm4(uint32_t& r0, uint32_t& r1,
                                      uint32_t& r2, uint32_t& r3, uint32_t addr) {
    asm volatile("ldmatrix.sync.aligned.m8n8.x4.shared.b16 {%0,%1,%2,%3}, [%4];"
                 : "=r"(r0), "=r"(r1), "=r"(r2), "=r"(r3) : "r"(addr));
}
__device__ __forceinline__ void mma_tf32(
    float& d0, float& d1, float& d2, float& d3,
    uint32_t a0, uint32_t a1, uint32_t a2, uint32_t a3,
    uint32_t b0, uint32_t b1)
{
    asm volatile(
        "mma.sync.aligned.m16n8k8.row.col.f32.tf32.tf32.f32 "
        "{%0,%1,%2,%3}, {%4,%5,%6,%7}, {%8,%9}, {%0,%1,%2,%3};\n"
        : "+f"(d0), "+f"(d1), "+f"(d2), "+f"(d3)
        : "r"(a0), "r"(a1), "r"(a2), "r"(a3), "r"(b0), "r"(b1));
}

// ---------------- weight transpose (8 matrices 1024x1024) ----------------
__global__ void __launch_bounds__(256) transpose_k(TPtrs tp)
{
    __shared__ float tile[32][33];
    const float* __restrict__ in = tp.src[blockIdx.z];
    float* __restrict__ out      = tp.dst[blockIdx.z];
    const int tx = threadIdx.x, ty = threadIdx.y;   // block (32, 8)
    const int x = blockIdx.x * 32 + tx;
    const int y0 = blockIdx.y * 32 + ty;
#pragma unroll
    for (int j = 0; j < 32; j += 8)
        tile[ty + j][tx] = in[(size_t)(y0 + j) * MM + x];
    __syncthreads();
    const int x2 = blockIdx.y * 32 + tx;
    const int y2 = blockIdx.x * 32 + ty;
#pragma unroll
    for (int j = 0; j < 32; j += 8)
        out[(size_t)(y2 + j) * MM + x2] = tile[tx][ty + j];
}

// ---------------- TF32 GEMM: cp.async 3-stage, SW128 layout, ldmatrix -----
// CTA tile 128x128, BK=32. smem tile: [row][k] rows of 128B, swizzled:
// byte(row, boff) = row*128 + (boff ^ ((row&7)<<4)).
#define BKT 32
#define TILE_B 16384                  // one operand tile (128 rows * 128B)
#define STAGE_B (2 * TILE_B)          // A + B per stage
#define NSTAGE 3
#define GEMM_SMEM (NSTAGE * STAGE_B)  // 96 KB

__device__ __forceinline__ void stage_tile(
    const float* __restrict__ Ablk, const float* __restrict__ Bblk,
    int K, int k0, uint32_t bufA, uint32_t bufB, int tid)
{
#pragma unroll
    for (int i = 0; i < 4; i++) {
        const int c = tid + 256 * i;
        const int row = c >> 3, q = c & 7;
        const uint32_t off = row * 128 + ((q * 16) ^ ((row & 7) << 4));
        cp16(bufA + off, Ablk + (size_t)row * K + k0 + q * 4);
        cp16(bufB + off, Bblk + (size_t)row * K + k0 + q * 4);
    }
}

template <int MODE>
__global__ void __launch_bounds__(256, 2) tf32gemm(GemmJobs jobs, int N, int K)
{
    extern __shared__ char dynsm[];
    const uint32_t sm0 = smem_u32(dynsm);

    const GemmJob job = jobs.j[blockIdx.z];
    const int tid = threadIdx.x, warp = tid >> 5, lane = tid & 31;
    const int tig = lane & 3, gid = lane >> 2;
    const int warpM = (warp >> 1) * 32;
    const int warpN = (warp & 1) * 64;
    const int bx = blockIdx.x, by = blockIdx.y;

    const float* __restrict__ Ablk = job.A + (size_t)by * 128 * K;
    const float* __restrict__ Bblk = job.BT + (size_t)bx * 128 * K;

    // ldmatrix lane addressing (precomputed row bases + swizzle keys)
    // A x4 -> {(m0:8,c0),(m8:16,c0),(m0:8,c0+1),(m8:16,c0+1)}
    uint32_t aBase[2], aKey[2];
    {
        const uint32_t r = (lane & 7) + ((lane >> 3) & 1) * 8;
        const uint32_t cb = (lane >> 4) * 16;                 // chunk sel
#pragma unroll
        for (int mf = 0; mf < 2; mf++) {
            const uint32_t row = warpM + mf * 16 + r;
            aBase[mf] = row * 128;
            aKey[mf]  = ((row & 7) << 4) ^ cb;   // fold chunk into key
        }
    }
    // B x4 -> {(n0:8,c0),(n0:8,c0+1),(n8:16,c0),(n8:16,c0+1)}
    uint32_t bBase[4], bKey[4];
    {
        const uint32_t r = (lane & 7) + ((lane >> 4) & 1) * 8;
        const uint32_t cb = ((lane >> 3) & 1) * 16;
#pragma unroll
        for (int p = 0; p < 4; p++) {
            const uint32_t row = warpN + p * 16 + r;
            bBase[p] = row * 128;
            bKey[p]  = ((row & 7) << 4) ^ cb;
        }
    }

    float acc[2][8][4];
#pragma unroll
    for (int i = 0; i < 2; i++)
#pragma unroll
        for (int j = 0; j < 8; j++)
#pragma unroll
            for (int q = 0; q < 4; q++) acc[i][j][q] = 0.f;

    const int nt = K / BKT;   // 32

    // prologue: stage tiles 0 and 1
    stage_tile(Ablk, Bblk, K, 0, sm0, sm0 + TILE_B, tid);
    cp_commit();
    stage_tile(Ablk, Bblk, K, BKT, sm0 + STAGE_B, sm0 + STAGE_B + TILE_B, tid);
    cp_commit();

    for (int t = 0; t < nt; t++) {
        cp_wait<1>();
        __syncthreads();

        if (t + 2 < nt) {
            const uint32_t sb = sm0 + ((t + 2) % NSTAGE) * STAGE_B;
            stage_tile(Ablk, Bblk, K, (t + 2) * BKT, sb, sb + TILE_B, tid);
        }
        cp_commit();

        const uint32_t abuf = sm0 + (t % NSTAGE) * STAGE_B;
        const uint32_t bbuf = abuf + TILE_B;

#pragma unroll
        for (int ks = 0; ks < BKT; ks += 8) {
            const uint32_t boff = ks * 4;
            uint32_t afr[2][4], bfr[8][2];
#pragma unroll
            for (int mf = 0; mf < 2; mf++)
                ldsm4(afr[mf][0], afr[mf][1], afr[mf][2], afr[mf][3],
                      abuf + aBase[mf] + (boff ^ aKey[mf]));
#pragma unroll
            for (int p = 0; p < 4; p++)
                ldsm4(bfr[2*p][0], bfr[2*p][1], bfr[2*p+1][0], bfr[2*p+1][1],
                      bbuf + bBase[p] + (boff ^ bKey[p]));
#pragma unroll
            for (int mf = 0; mf < 2; mf++)
#pragma unroll
                for (int nf = 0; nf < 8; nf++)
                    mma_tf32(acc[mf][nf][0], acc[mf][nf][1],
                             acc[mf][nf][2], acc[mf][nf][3],
                             afr[mf][0], afr[mf][1], afr[mf][2], afr[mf][3],
                             bfr[nf][0], bfr[nf][1]);
        }
        __syncthreads();
    }

    // epilogue
    const float* __restrict__ bias  = job.bias;
    const float* __restrict__ extra = job.extra;
    float* __restrict__ C           = job.C;
    const int row0 = by * 128 + warpM;
    const int col0 = bx * 128 + warpN;

#pragma unroll
    for (int mf = 0; mf < 2; mf++) {
#pragma unroll
        for (int nf = 0; nf < 8; nf++) {
            const int c = col0 + nf * 8 + 2 * tig;
            float bv0 = 0.f, bv1 = 0.f;
            if (bias) { bv0 = bias[c]; bv1 = bias[c + 1]; }
#pragma unroll
            for (int half = 0; half < 2; half++) {
                const int r = row0 + mf * 16 + gid + half * 8;
                float v0 = acc[mf][nf][half * 2 + 0] + bv0;
                float v1 = acc[mf][nf][half * 2 + 1] + bv1;
                if (MODE == 1) {
                    const float2 e = *(const float2*)(extra + (size_t)r * N + c);
                    v0 += e.x; v1 += e.y;
                } else if (MODE == 2) {
                    const float2 e = *(const float2*)(extra + (size_t)(r >> 4) * N + c);
                    v0 += e.x; v1 += e.y;
                }
                float2 out = { v0, v1 };
                *(float2*)(C + (size_t)r * N + c) = out;
            }
        }
    }
}

// generic-mode variant: per-job runtime mode (big fused launch)
__global__ void __launch_bounds__(256, 2) tf32gemm_rt(GemmJobs jobs, int N, int K);

// Reuse template through a runtime dispatcher kernel is not possible; instead
// instantiate MODE=3 meaning "read job.mode at runtime".
template __global__ void tf32gemm<0>(GemmJobs, int, int);

// ---------------- attention kernel ----------------
__global__ void __launch_bounds__(256) attn_kernel(
    const float* __restrict__ m_state, float* __restrict__ mp_out)
{
    const int bh = blockIdx.x;
    const int b = bh >> 3;
    const int h = bh & 7;
    const int tid = threadIdx.x;

    __shared__ float kv[17][128];
    __shared__ float sc[16][18];

    const float* mbase = m_state + (size_t)b * SS * MM + h * HSZ;
    for (int idx = tid; idx < 16 * 128; idx += 256) {
        int j = idx >> 7, d = idx & 127;
        kv[j][d] = mbase[(size_t)j * MM + d];
    }
    if (tid < 128) kv[16][tid] = g_dense[(size_t)b * MM + h * HSZ + tid];
    __syncthreads();

    const int warp = tid >> 5, lane = tid & 31;
    for (int s = warp; s < 16 * 17; s += 8) {
        const int i = s / 17, j = s % 17;
        float sum = 0.f;
#pragma unroll
        for (int t = 0; t < 4; t++)
            sum += kv[i][lane + t * 32] * kv[j][lane + t * 32];
#pragma unroll
        for (int off = 16; off; off >>= 1)
            sum += __shfl_xor_sync(0xffffffff, sum, off);
        if (lane == 0) sc[i][j] = sum * 0.08838834764831845f;
    }
    __syncthreads();

    if (tid < 16) {
        float mx = -1e30f;
#pragma unroll
        for (int j = 0; j < 17; j++) mx = fmaxf(mx, sc[tid][j]);
        float sum = 0.f;
#pragma unroll
        for (int j = 0; j < 17; j++) {
            float e = expf(sc[tid][j] - mx);
            sc[tid][j] = e;
            sum += e;
        }
        const float inv = 1.f / sum;
#pragma unroll
        for (int j = 0; j < 17; j++) sc[tid][j] *= inv;
    }
    __syncthreads();

    for (int idx = tid; idx < 16 * 128; idx += 256) {
        const int i = idx >> 7, d = idx & 127;
        float a = 0.f;
#pragma unroll
        for (int j = 0; j < 17; j++) a += sc[i][j] * kv[j][d];
        mp_out[((size_t)b * SS + i) * MM + h * HSZ + d] = kv[i][d] + a;
    }
}

// ---------------- final elementwise gating ----------------
__device__ __forceinline__ float sigm(float x) { return 1.f / (1.f + expf(-x)); }

__global__ void __launch_bounds__(256) final_kernel(
    const float4* __restrict__ m, const float4* __restrict__ mp2,
    const float4* __restrict__ gf, const float4* __restrict__ gi,
    const float4* __restrict__ go, float4* __restrict__ out)
{
    const size_t i = (size_t)blockIdx.x * 256 + threadIdx.x;
    float4 mv = m[i], p = mp2[i], f = gf[i], ig = gi[i], og = go[i];
    float4 nm, nh;

    nm.x = sigm(mv.x * sigm(f.x) + 1.f) + p.x * sigm(sigm(ig.x));
    nm.y = sigm(mv.y * sigm(f.y) + 1.f) + p.y * sigm(sigm(ig.y));
    nm.z = sigm(mv.z * sigm(f.z) + 1.f) + p.z * sigm(sigm(ig.z));
    nm.w = sigm(mv.w * sigm(f.w) + 1.f) + p.w * sigm(sigm(ig.w));

    nh.x = tanhf(mv.x) * sigm(sigm(og.x));
    nh.y = tanhf(mv.y) * sigm(sigm(og.y));
    nh.z = tanhf(mv.z) * sigm(sigm(og.z));
    nh.w = tanhf(mv.w) * sigm(sigm(og.w));

    out[i] = nm;
    out[(N_ELEM / 4) + i] = nh;
}

// ---------------- launch ----------------
extern "C" void kernel_launch(void* const* d_in, const int* in_sizes, int n_in,
                              void* d_out, int out_size)
{
    const float* inputs  = (const float*)d_in[0];
    const float* h_state = (const float*)d_in[1];
    const float* m_state = (const float*)d_in[2];
    const float* W_emb   = (const float*)d_in[3];
    const float* b_emb   = (const float*)d_in[4];
    const float* W_g     = (const float*)d_in[5];
    const float* b_g     = (const float*)d_in[6];
    const float* W_wf    = (const float*)d_in[7];
    const float* W_wi    = (const float*)d_in[8];
    const float* W_wo    = (const float*)d_in[9];
    const float* W_uf    = (const float*)d_in[10];
    const float* b_uf    = (const float*)d_in[11];
    const float* W_ui    = (const float*)d_in[12];
    const float* b_ui    = (const float*)d_in[13];
    const float* W_uo    = (const float*)d_in[14];
    const float* b_uo    = (const float*)d_in[15];

    float *p_dense, *p_xf, *p_xi, *p_xo, *p_mp, *p_mp2, *p_gf, *p_gi, *p_go, *p_wT;
    cudaGetSymbolAddress((void**)&p_dense, g_dense);
    cudaGetSymbolAddress((void**)&p_xf, g_xf);
    cudaGetSymbolAddress((void**)&p_xi, g_xi);
    cudaGetSymbolAddress((void**)&p_xo, g_xo);
    cudaGetSymbolAddress((void**)&p_mp, g_mp);
    cudaGetSymbolAddress((void**)&p_mp2, g_mp2);
    cudaGetSymbolAddress((void**)&p_gf, g_gf);
    cudaGetSymbolAddress((void**)&p_gi, g_gi);
    cudaGetSymbolAddress((void**)&p_go, g_go);
    cudaGetSymbolAddress((void**)&p_wT, g_wT);

    float* wt[8];
    for (int i = 0; i < 8; i++) wt[i] = p_wT + (size_t)i * MM * MM;

    cudaFuncSetAttribute(tf32gemm<0>, cudaFuncAttributeMaxDynamicSharedMemorySize, GEMM_SMEM);
    cudaFuncSetAttribute(tf32gemm<1>, cudaFuncAttributeMaxDynamicSharedMemorySize, GEMM_SMEM);
    cudaFuncSetAttribute(tf32gemm<2>, cudaFuncAttributeMaxDynamicSharedMemorySize, GEMM_SMEM);

    // 0) transpose all 8 weight matrices: order emb, wf, wi, wo, uf, ui, uo, g
    {
        TPtrs tp;
        tp.src[0] = W_emb; tp.src[1] = W_wf; tp.src[2] = W_wi; tp.src[3] = W_wo;
        tp.src[4] = W_uf;  tp.src[5] = W_ui; tp.src[6] = W_uo; tp.src[7] = W_g;
        for (int i = 0; i < 8; i++) tp.dst[i] = wt[i];
        transpose_k<<<dim3(32, 32, 8), dim3(32, 8)>>>(tp);
    }

    // 1) 4 input projections in one launch
    {
        GemmJobs gj;
        gj.j[0] = { inputs, wt[0], b_emb, nullptr, p_dense, 0 };
        gj.j[1] = { inputs, wt[1], nullptr, nullptr, p_xf, 0 };
        gj.j[2] = { inputs, wt[2], nullptr, nullptr, p_xi, 0 };
        gj.j[3] = { inputs, wt[3], nullptr, nullptr, p_xo, 0 };
        tf32gemm<0><<<dim3(MM/128, BB/128, 4), 256, GEMM_SMEM>>>(gj, MM, DD);
    }

    // 2) attention -> memory proposal (needs g_dense)
    attn_kernel<<<BB * HH, 256>>>(m_state, p_mp);

    // 3) gates f/i/o (mode 2, one launch)
    {
        GemmJobs gj;
        gj.j[0] = { h_state, wt[4], b_uf, p_xf, p_gf, 2 };
        gj.j[1] = { h_state, wt[5], b_ui, p_xi, p_gi, 2 };
        gj.j[2] = { h_state, wt[6], b_uo, p_xo, p_go, 2 };
        gj.j[3] = gj.j[0];
        tf32gemm<2><<<dim3(MM/128, ROWS_L/128, 3), 256, GEMM_SMEM>>>(gj, MM, MM);
    }

    // 4) mp2 = mp @ W_g + b_g + mp (mode 1)
    {
        GemmJobs gj;
        gj.j[0] = { p_mp, wt[7], b_g, p_mp, p_mp2, 1 };
        gj.j[1] = gj.j[2] = gj.j[3] = gj.j[0];
        tf32gemm<1><<<dim3(MM/128, ROWS_L/128, 1), 256, GEMM_SMEM>>>(gj, MM, MM);
    }

    // 5) final gating
    final_kernel<<<(unsigned)(N_ELEM / 4 / 256), 256>>>(
        (const float4*)m_state, (const float4*)p_mp2,
        (const float4*)p_gf, (const float4*)p_gi, (const float4*)p_go,
        (float4*)d_out);
}

// round 10
// speedup vs baseline: 4.7296x; 1.0974x over previous
#include <cuda_runtime.h>
#include <cstdint>
#include <cstddef>

// Problem constants
#define BB 256
#define SS 16
#define HH 8
#define HSZ 128
#define DD 1024
#define MM 1024
#define ROWS_L (BB*SS)               // 4096
#define N_ELEM ((size_t)ROWS_L*MM)   // 4,194,304

// ---------------- scratch ----------------
__device__ float g_dense[BB*MM];
__device__ float g_xf[BB*MM];
__device__ float g_xi[BB*MM];
__device__ float g_xo[BB*MM];
__device__ float g_mp[ROWS_L*MM];
__device__ float g_mp2[ROWS_L*MM];
__device__ float g_gf[ROWS_L*MM];
__device__ float g_gi[ROWS_L*MM];
__device__ float g_go[ROWS_L*MM];
__device__ float g_wT[8][MM*MM];     // transposed weights [N][K]

struct GemmJob {
    const float* A;      // [Mrows, K] row-major (k-contiguous)
    const float* BT;     // [N, K] row-major (transposed weight, k-contiguous)
    const float* bias;   // [N] or null
    const float* extra;  // residual per mode
    float*       C;      // [Mrows, N]
    int mode;            // 0: none, 1: +extra[r][c], 2: +extra[r>>4][c]
};
struct GemmJobs { GemmJob j[4]; };
struct TPtrs { const float* src[8]; float* dst[8]; };

__device__ __forceinline__ uint32_t smem_u32(const void* p) {
    return (uint32_t)__cvta_generic_to_shared(p);
}
__device__ __forceinline__ void cp16(uint32_t dst, const void* src) {
    asm volatile("cp.async.cg.shared.global [%0], [%1], 16;" :: "r"(dst), "l"(src));
}
__device__ __forceinline__ void cp_commit() {
    asm volatile("cp.async.commit_group;" ::: "memory");
}
template <int N>
__device__ __forceinline__ void cp_wait() {
    asm volatile("cp.async.wait_group %0;" :: "n"(N) : "memory");
}
__device__ __forceinline__ void ldsm4(uint32_t& r0, uint32_t& r1,
                                      uint32_t& r2, uint32_t& r3, uint32_t addr) {
    asm volatile("ldmatrix.sync.aligned.m8n8.x4.shared.b16 {%0,%1,%2,%3}, [%4];"
                 : "=r"(r0), "=r"(r1), "=r"(r2), "=r"(r3) : "r"(addr));
}
__device__ __forceinline__ void mma_tf32(
    float& d0, float& d1, float& d2, float& d3,
    uint32_t a0, uint32_t a1, uint32_t a2, uint32_t a3,
    uint32_t b0, uint32_t b1)
{
    asm volatile(
        "mma.sync.aligned.m16n8k8.row.col.f32.tf32.tf32.f32 "
        "{%0,%1,%2,%3}, {%4,%5,%6,%7}, {%8,%9}, {%0,%1,%2,%3};\n"
        : "+f"(d0), "+f"(d1), "+f"(d2), "+f"(d3)
        : "r"(a0), "r"(a1), "r"(a2), "r"(a3), "r"(b0), "r"(b1));
}

// ---------------- weight transpose (8 matrices 1024x1024) ----------------
__global__ void __launch_bounds__(256) transpose_k(TPtrs tp)
{
    __shared__ float tile[32][33];
    const float* __restrict__ in = tp.src[blockIdx.z];
    float* __restrict__ out      = tp.dst[blockIdx.z];
    const int tx = threadIdx.x, ty = threadIdx.y;   // block (32, 8)
    const int x = blockIdx.x * 32 + tx;
    const int y0 = blockIdx.y * 32 + ty;
#pragma unroll
    for (int j = 0; j < 32; j += 8)
        tile[ty + j][tx] = in[(size_t)(y0 + j) * MM + x];
    __syncthreads();
    const int x2 = blockIdx.y * 32 + tx;
    const int y2 = blockIdx.x * 32 + ty;
#pragma unroll
    for (int j = 0; j < 32; j += 8)
        out[(size_t)(y2 + j) * MM + x2] = tile[tx][ty + j];
}

// ---------------- TF32 GEMM: cp.async 3-stage, SW128 layout, ldmatrix -----
// CTA tile 128x128, BK=32. smem tile: [row][k] rows of 128B, swizzled:
// byte(row, boff) = row*128 + (boff ^ ((row&7)<<4)).
// MODE 0/1/2 compile-time; MODE 3 = read job.mode at runtime.
#define BKT 32
#define TILE_B 16384
#define STAGE_B (2 * TILE_B)
#define NSTAGE 3
#define GEMM_SMEM (NSTAGE * STAGE_B)  // 96 KB

__device__ __forceinline__ void stage_tile(
    const float* __restrict__ Ablk, const float* __restrict__ Bblk,
    int K, int k0, uint32_t bufA, uint32_t bufB, int tid)
{
#pragma unroll
    for (int i = 0; i < 4; i++) {
        const int c = tid + 256 * i;
        const int row = c >> 3, q = c & 7;
        const uint32_t off = row * 128 + ((q * 16) ^ ((row & 7) << 4));
        cp16(bufA + off, Ablk + (size_t)row * K + k0 + q * 4);
        cp16(bufB + off, Bblk + (size_t)row * K + k0 + q * 4);
    }
}

template <int MODE>
__global__ void __launch_bounds__(256, 2) tf32gemm(GemmJobs jobs, int N, int K)
{
    extern __shared__ char dynsm[];
    const uint32_t sm0 = smem_u32(dynsm);

    const GemmJob job = jobs.j[blockIdx.z];
    const int tid = threadIdx.x, warp = tid >> 5, lane = tid & 31;
    const int tig = lane & 3, gid = lane >> 2;
    const int warpM = (warp >> 1) * 32;
    const int warpN = (warp & 1) * 64;
    const int bx = blockIdx.x, by = blockIdx.y;

    const float* __restrict__ Ablk = job.A + (size_t)by * 128 * K;
    const float* __restrict__ Bblk = job.BT + (size_t)bx * 128 * K;

    // ldmatrix lane addressing (precomputed row bases + swizzle keys)
    uint32_t aBase[2], aKey[2];
    {
        const uint32_t r = (lane & 7) + ((lane >> 3) & 1) * 8;
        const uint32_t cb = (lane >> 4) * 16;
#pragma unroll
        for (int mf = 0; mf < 2; mf++) {
            const uint32_t row = warpM + mf * 16 + r;
            aBase[mf] = row * 128;
            aKey[mf]  = ((row & 7) << 4) ^ cb;
        }
    }
    uint32_t bBase[4], bKey[4];
    {
        const uint32_t r = (lane & 7) + ((lane >> 4) & 1) * 8;
        const uint32_t cb = ((lane >> 3) & 1) * 16;
#pragma unroll
        for (int p = 0; p < 4; p++) {
            const uint32_t row = warpN + p * 16 + r;
            bBase[p] = row * 128;
            bKey[p]  = ((row & 7) << 4) ^ cb;
        }
    }

    float acc[2][8][4];
#pragma unroll
    for (int i = 0; i < 2; i++)
#pragma unroll
        for (int j = 0; j < 8; j++)
#pragma unroll
            for (int q = 0; q < 4; q++) acc[i][j][q] = 0.f;

    const int nt = K / BKT;   // 32

    // prologue: stage tiles 0 and 1
    stage_tile(Ablk, Bblk, K, 0, sm0, sm0 + TILE_B, tid);
    cp_commit();
    stage_tile(Ablk, Bblk, K, BKT, sm0 + STAGE_B, sm0 + STAGE_B + TILE_B, tid);
    cp_commit();

    for (int t = 0; t < nt; t++) {
        cp_wait<1>();
        __syncthreads();   // single barrier per tile: also orders compute(t-1)
                           // before staging into slot (t+2)%3 == (t-1)%3

        if (t + 2 < nt) {
            const uint32_t sb = sm0 + ((t + 2) % NSTAGE) * STAGE_B;
            stage_tile(Ablk, Bblk, K, (t + 2) * BKT, sb, sb + TILE_B, tid);
        }
        cp_commit();

        const uint32_t abuf = sm0 + (t % NSTAGE) * STAGE_B;
        const uint32_t bbuf = abuf + TILE_B;

#pragma unroll
        for (int ks = 0; ks < BKT; ks += 8) {
            const uint32_t boff = ks * 4;
            uint32_t afr[2][4], bfr[8][2];
#pragma unroll
            for (int mf = 0; mf < 2; mf++)
                ldsm4(afr[mf][0], afr[mf][1], afr[mf][2], afr[mf][3],
                      abuf + aBase[mf] + (boff ^ aKey[mf]));
#pragma unroll
            for (int p = 0; p < 4; p++)
                ldsm4(bfr[2*p][0], bfr[2*p][1], bfr[2*p+1][0], bfr[2*p+1][1],
                      bbuf + bBase[p] + (boff ^ bKey[p]));
#pragma unroll
            for (int mf = 0; mf < 2; mf++)
#pragma unroll
                for (int nf = 0; nf < 8; nf++)
                    mma_tf32(acc[mf][nf][0], acc[mf][nf][1],
                             acc[mf][nf][2], acc[mf][nf][3],
                             afr[mf][0], afr[mf][1], afr[mf][2], afr[mf][3],
                             bfr[nf][0], bfr[nf][1]);
        }
    }

    // epilogue
    const float* __restrict__ bias  = job.bias;
    const float* __restrict__ extra = job.extra;
    float* __restrict__ C           = job.C;
    const int md = (MODE == 3) ? job.mode : MODE;
    const int row0 = by * 128 + warpM;
    const int col0 = bx * 128 + warpN;

#pragma unroll
    for (int mf = 0; mf < 2; mf++) {
#pragma unroll
        for (int nf = 0; nf < 8; nf++) {
            const int c = col0 + nf * 8 + 2 * tig;
            float bv0 = 0.f, bv1 = 0.f;
            if (bias) { bv0 = bias[c]; bv1 = bias[c + 1]; }
#pragma unroll
            for (int half = 0; half < 2; half++) {
                const int r = row0 + mf * 16 + gid + half * 8;
                float v0 = acc[mf][nf][half * 2 + 0] + bv0;
                float v1 = acc[mf][nf][half * 2 + 1] + bv1;
                if (md == 1) {
                    const float2 e = *(const float2*)(extra + (size_t)r * N + c);
                    v0 += e.x; v1 += e.y;
                } else if (md == 2) {
                    const float2 e = *(const float2*)(extra + (size_t)(r >> 4) * N + c);
                    v0 += e.x; v1 += e.y;
                }
                float2 out = { v0, v1 };
                *(float2*)(C + (size_t)r * N + c) = out;
            }
        }
    }
}

// ---------------- attention kernel ----------------
__global__ void __launch_bounds__(256) attn_kernel(
    const float* __restrict__ m_state, float* __restrict__ mp_out)
{
    const int bh = blockIdx.x;
    const int b = bh >> 3;
    const int h = bh & 7;
    const int tid = threadIdx.x;

    __shared__ float kv[17][128];
    __shared__ float sc[16][18];

    const float* mbase = m_state + (size_t)b * SS * MM + h * HSZ;
    for (int idx = tid; idx < 16 * 128; idx += 256) {
        int j = idx >> 7, d = idx & 127;
        kv[j][d] = mbase[(size_t)j * MM + d];
    }
    if (tid < 128) kv[16][tid] = g_dense[(size_t)b * MM + h * HSZ + tid];
    __syncthreads();

    const int warp = tid >> 5, lane = tid & 31;
    for (int s = warp; s < 16 * 17; s += 8) {
        const int i = s / 17, j = s % 17;
        float sum = 0.f;
#pragma unroll
        for (int t = 0; t < 4; t++)
            sum += kv[i][lane + t * 32] * kv[j][lane + t * 32];
#pragma unroll
        for (int off = 16; off; off >>= 1)
            sum += __shfl_xor_sync(0xffffffff, sum, off);
        if (lane == 0) sc[i][j] = sum * 0.08838834764831845f;
    }
    __syncthreads();

    if (tid < 16) {
        float mx = -1e30f;
#pragma unroll
        for (int j = 0; j < 17; j++) mx = fmaxf(mx, sc[tid][j]);
        float sum = 0.f;
#pragma unroll
        for (int j = 0; j < 17; j++) {
            float e = expf(sc[tid][j] - mx);
            sc[tid][j] = e;
            sum += e;
        }
        const float inv = 1.f / sum;
#pragma unroll
        for (int j = 0; j < 17; j++) sc[tid][j] *= inv;
    }
    __syncthreads();

    for (int idx = tid; idx < 16 * 128; idx += 256) {
        const int i = idx >> 7, d = idx & 127;
        float a = 0.f;
#pragma unroll
        for (int j = 0; j < 17; j++) a += sc[i][j] * kv[j][d];
        mp_out[((size_t)b * SS + i) * MM + h * HSZ + d] = kv[i][d] + a;
    }
}

// ---------------- final elementwise gating ----------------
__device__ __forceinline__ float sigm(float x) { return 1.f / (1.f + expf(-x)); }

__global__ void __launch_bounds__(256) final_kernel(
    const float4* __restrict__ m, const float4* __restrict__ mp2,
    const float4* __restrict__ gf, const float4* __restrict__ gi,
    const float4* __restrict__ go, float4* __restrict__ out)
{
    const size_t i = (size_t)blockIdx.x * 256 + threadIdx.x;
    float4 mv = m[i], p = mp2[i], f = gf[i], ig = gi[i], og = go[i];
    float4 nm, nh;

    nm.x = sigm(mv.x * sigm(f.x) + 1.f) + p.x * sigm(sigm(ig.x));
    nm.y = sigm(mv.y * sigm(f.y) + 1.f) + p.y * sigm(sigm(ig.y));
    nm.z = sigm(mv.z * sigm(f.z) + 1.f) + p.z * sigm(sigm(ig.z));
    nm.w = sigm(mv.w * sigm(f.w) + 1.f) + p.w * sigm(sigm(ig.w));

    nh.x = tanhf(mv.x) * sigm(sigm(og.x));
    nh.y = tanhf(mv.y) * sigm(sigm(og.y));
    nh.z = tanhf(mv.z) * sigm(sigm(og.z));
    nh.w = tanhf(mv.w) * sigm(sigm(og.w));

    out[i] = nm;
    out[(N_ELEM / 4) + i] = nh;
}

// ---------------- launch ----------------
extern "C" void kernel_launch(void* const* d_in, const int* in_sizes, int n_in,
                              void* d_out, int out_size)
{
    const float* inputs  = (const float*)d_in[0];
    const float* h_state = (const float*)d_in[1];
    const float* m_state = (const float*)d_in[2];
    const float* W_emb   = (const float*)d_in[3];
    const float* b_emb   = (const float*)d_in[4];
    const float* W_g     = (const float*)d_in[5];
    const float* b_g     = (const float*)d_in[6];
    const float* W_wf    = (const float*)d_in[7];
    const float* W_wi    = (const float*)d_in[8];
    const float* W_wo    = (const float*)d_in[9];
    const float* W_uf    = (const float*)d_in[10];
    const float* b_uf    = (const float*)d_in[11];
    const float* W_ui    = (const float*)d_in[12];
    const float* b_ui    = (const float*)d_in[13];
    const float* W_uo    = (const float*)d_in[14];
    const float* b_uo    = (const float*)d_in[15];

    float *p_dense, *p_xf, *p_xi, *p_xo, *p_mp, *p_mp2, *p_gf, *p_gi, *p_go, *p_wT;
    cudaGetSymbolAddress((void**)&p_dense, g_dense);
    cudaGetSymbolAddress((void**)&p_xf, g_xf);
    cudaGetSymbolAddress((void**)&p_xi, g_xi);
    cudaGetSymbolAddress((void**)&p_xo, g_xo);
    cudaGetSymbolAddress((void**)&p_mp, g_mp);
    cudaGetSymbolAddress((void**)&p_mp2, g_mp2);
    cudaGetSymbolAddress((void**)&p_gf, g_gf);
    cudaGetSymbolAddress((void**)&p_gi, g_gi);
    cudaGetSymbolAddress((void**)&p_go, g_go);
    cudaGetSymbolAddress((void**)&p_wT, g_wT);

    float* wt[8];
    for (int i = 0; i < 8; i++) wt[i] = p_wT + (size_t)i * MM * MM;

    cudaFuncSetAttribute(tf32gemm<0>, cudaFuncAttributeMaxDynamicSharedMemorySize, GEMM_SMEM);
    cudaFuncSetAttribute(tf32gemm<3>, cudaFuncAttributeMaxDynamicSharedMemorySize, GEMM_SMEM);

    // 0) transpose all 8 weight matrices: order emb, wf, wi, wo, uf, ui, uo, g
    {
        TPtrs tp;
        tp.src[0] = W_emb; tp.src[1] = W_wf; tp.src[2] = W_wi; tp.src[3] = W_wo;
        tp.src[4] = W_uf;  tp.src[5] = W_ui; tp.src[6] = W_uo; tp.src[7] = W_g;
        for (int i = 0; i < 8; i++) tp.dst[i] = wt[i];
        transpose_k<<<dim3(32, 32, 8), dim3(32, 8)>>>(tp);
    }

    // 1) 4 input projections in one launch
    {
        GemmJobs gj;
        gj.j[0] = { inputs, wt[0], b_emb, nullptr, p_dense, 0 };
        gj.j[1] = { inputs, wt[1], nullptr, nullptr, p_xf, 0 };
        gj.j[2] = { inputs, wt[2], nullptr, nullptr, p_xi, 0 };
        gj.j[3] = { inputs, wt[3], nullptr, nullptr, p_xo, 0 };
        tf32gemm<0><<<dim3(MM/128, BB/128, 4), 256, GEMM_SMEM>>>(gj, MM, DD);
    }

    // 2) attention -> memory proposal (needs g_dense)
    attn_kernel<<<BB * HH, 256>>>(m_state, p_mp);

    // 3) gates f/i/o + mp2 in ONE launch (runtime mode per job)
    {
        GemmJobs gj;
        gj.j[0] = { h_state, wt[4], b_uf, p_xf, p_gf, 2 };
        gj.j[1] = { h_state, wt[5], b_ui, p_xi, p_gi, 2 };
        gj.j[2] = { h_state, wt[6], b_uo, p_xo, p_go, 2 };
        gj.j[3] = { p_mp,    wt[7], b_g,  p_mp, p_mp2, 1 };
        tf32gemm<3><<<dim3(MM/128, ROWS_L/128, 4), 256, GEMM_SMEM>>>(gj, MM, MM);
    }

    // 4) final gating
    final_kernel<<<(unsigned)(N_ELEM / 4 / 256), 256>>>(
        (const float4*)m_state, (const float4*)p_mp2,
        (const float4*)p_gf, (const float4*)p_gi, (const float4*)p_go,
        (float4*)d_out);
}

// round 11
// speedup vs baseline: 4.8651x; 1.0286x over previous
#include <cuda_runtime.h>
#include <cstdint>
#include <cstddef>

// Problem constants
#define BB 256
#define SS 16
#define HH 8
#define HSZ 128
#define DD 1024
#define MM 1024
#define ROWS_L (BB*SS)               // 4096
#define N_ELEM ((size_t)ROWS_L*MM)   // 4,194,304

// ---------------- scratch ----------------
__device__ float g_dense[BB*MM];
__device__ float g_xf[BB*MM];
__device__ float g_xi[BB*MM];
__device__ float g_xo[BB*MM];
__device__ float g_mp[ROWS_L*MM];
__device__ float g_mp2[ROWS_L*MM];
__device__ float g_gf[ROWS_L*MM];
__device__ float g_gi[ROWS_L*MM];
__device__ float g_go[ROWS_L*MM];
__device__ float g_wT[8][MM*MM];     // transposed weights [N][K]

struct MegaJobs {                    // 7 independent GEMMs, all K=1024, N=1024
    const float* A[7];
    const float* BT[7];
    const float* bias[7];
    float*       C[7];
};
struct GemmJob {
    const float* A;
    const float* BT;
    const float* bias;
    const float* extra;
    float*       C;
};
struct TPtrs { const float* src[8]; float* dst[8]; };

__device__ __forceinline__ uint32_t smem_u32(const void* p) {
    return (uint32_t)__cvta_generic_to_shared(p);
}
__device__ __forceinline__ void cp16(uint32_t dst, const void* src) {
    asm volatile("cp.async.cg.shared.global [%0], [%1], 16;" :: "r"(dst), "l"(src));
}
__device__ __forceinline__ void cp_commit() {
    asm volatile("cp.async.commit_group;" ::: "memory");
}
template <int N>
__device__ __forceinline__ void cp_wait() {
    asm volatile("cp.async.wait_group %0;" :: "n"(N) : "memory");
}
__device__ __forceinline__ void ldsm4(uint32_t& r0, uint32_t& r1,
                                      uint32_t& r2, uint32_t& r3, uint32_t addr) {
    asm volatile("ldmatrix.sync.aligned.m8n8.x4.shared.b16 {%0,%1,%2,%3}, [%4];"
                 : "=r"(r0), "=r"(r1), "=r"(r2), "=r"(r3) : "r"(addr));
}
__device__ __forceinline__ void mma_tf32(
    float& d0, float& d1, float& d2, float& d3,
    uint32_t a0, uint32_t a1, uint32_t a2, uint32_t a3,
    uint32_t b0, uint32_t b1)
{
    asm volatile(
        "mma.sync.aligned.m16n8k8.row.col.f32.tf32.tf32.f32 "
        "{%0,%1,%2,%3}, {%4,%5,%6,%7}, {%8,%9}, {%0,%1,%2,%3};\n"
        : "+f"(d0), "+f"(d1), "+f"(d2), "+f"(d3)
        : "r"(a0), "r"(a1), "r"(a2), "r"(a3), "r"(b0), "r"(b1));
}

// ---------------- weight transpose (8 matrices 1024x1024) ----------------
__global__ void __launch_bounds__(256) transpose_k(TPtrs tp)
{
    __shared__ float tile[32][33];
    const float* __restrict__ in = tp.src[blockIdx.z];
    float* __restrict__ out      = tp.dst[blockIdx.z];
    const int tx = threadIdx.x, ty = threadIdx.y;   // block (32, 8)
    const int x = blockIdx.x * 32 + tx;
    const int y0 = blockIdx.y * 32 + ty;
#pragma unroll
    for (int j = 0; j < 32; j += 8)
        tile[ty + j][tx] = in[(size_t)(y0 + j) * MM + x];
    __syncthreads();
    const int x2 = blockIdx.y * 32 + tx;
    const int y2 = blockIdx.x * 32 + ty;
#pragma unroll
    for (int j = 0; j < 32; j += 8)
        out[(size_t)(y2 + j) * MM + x2] = tile[tx][ty + j];
}

// ---------------- TF32 GEMM core: cp.async 3-stage, SW128, ldmatrix ------
#define BKT 32
#define TILE_B 16384
#define STAGE_B (2 * TILE_B)
#define NSTAGE 3
#define GEMM_SMEM (NSTAGE * STAGE_B)  // 96 KB

__device__ __forceinline__ void stage_tile(
    const float* __restrict__ Ablk, const float* __restrict__ Bblk,
    int K, int k0, uint32_t bufA, uint32_t bufB, int tid)
{
#pragma unroll
    for (int i = 0; i < 4; i++) {
        const int c = tid + 256 * i;
        const int row = c >> 3, q = c & 7;
        const uint32_t off = row * 128 + ((q * 16) ^ ((row & 7) << 4));
        cp16(bufA + off, Ablk + (size_t)row * K + k0 + q * 4);
        cp16(bufB + off, Bblk + (size_t)row * K + k0 + q * 4);
    }
}

// MODE 0: C = A@B + bias;  MODE 1: += extra[r][c] (residual)
template <int MODE>
__device__ __forceinline__ void gemm_core(
    const float* __restrict__ A, const float* __restrict__ BT,
    const float* __restrict__ bias, const float* __restrict__ extra,
    float* __restrict__ C, int N, int K, int bx, int by, char* dynsm)
{
    const uint32_t sm0 = smem_u32(dynsm);
    const int tid = threadIdx.x, warp = tid >> 5, lane = tid & 31;
    const int tig = lane & 3, gid = lane >> 2;
    const int warpM = (warp >> 1) * 32;
    const int warpN = (warp & 1) * 64;

    const float* __restrict__ Ablk = A + (size_t)by * 128 * K;
    const float* __restrict__ Bblk = BT + (size_t)bx * 128 * K;

    uint32_t aBase[2], aKey[2];
    {
        const uint32_t r = (lane & 7) + ((lane >> 3) & 1) * 8;
        const uint32_t cb = (lane >> 4) * 16;
#pragma unroll
        for (int mf = 0; mf < 2; mf++) {
            const uint32_t row = warpM + mf * 16 + r;
            aBase[mf] = row * 128;
            aKey[mf]  = ((row & 7) << 4) ^ cb;
        }
    }
    uint32_t bBase[4], bKey[4];
    {
        const uint32_t r = (lane & 7) + ((lane >> 4) & 1) * 8;
        const uint32_t cb = ((lane >> 3) & 1) * 16;
#pragma unroll
        for (int p = 0; p < 4; p++) {
            const uint32_t row = warpN + p * 16 + r;
            bBase[p] = row * 128;
            bKey[p]  = ((row & 7) << 4) ^ cb;
        }
    }

    float acc[2][8][4];
#pragma unroll
    for (int i = 0; i < 2; i++)
#pragma unroll
        for (int j = 0; j < 8; j++)
#pragma unroll
            for (int q = 0; q < 4; q++) acc[i][j][q] = 0.f;

    const int nt = K / BKT;

    stage_tile(Ablk, Bblk, K, 0, sm0, sm0 + TILE_B, tid);
    cp_commit();
    stage_tile(Ablk, Bblk, K, BKT, sm0 + STAGE_B, sm0 + STAGE_B + TILE_B, tid);
    cp_commit();

    for (int t = 0; t < nt; t++) {
        cp_wait<1>();
        __syncthreads();   // single barrier: also orders compute(t-1) before
                           // staging into slot (t+2)%3 == (t-1)%3

        if (t + 2 < nt) {
            const uint32_t sb = sm0 + ((t + 2) % NSTAGE) * STAGE_B;
            stage_tile(Ablk, Bblk, K, (t + 2) * BKT, sb, sb + TILE_B, tid);
        }
        cp_commit();

        const uint32_t abuf = sm0 + (t % NSTAGE) * STAGE_B;
        const uint32_t bbuf = abuf + TILE_B;

#pragma unroll
        for (int ks = 0; ks < BKT; ks += 8) {
            const uint32_t boff = ks * 4;
            uint32_t afr[2][4], bfr[8][2];
#pragma unroll
            for (int mf = 0; mf < 2; mf++)
                ldsm4(afr[mf][0], afr[mf][1], afr[mf][2], afr[mf][3],
                      abuf + aBase[mf] + (boff ^ aKey[mf]));
#pragma unroll
            for (int p = 0; p < 4; p++)
                ldsm4(bfr[2*p][0], bfr[2*p][1], bfr[2*p+1][0], bfr[2*p+1][1],
                      bbuf + bBase[p] + (boff ^ bKey[p]));
#pragma unroll
            for (int mf = 0; mf < 2; mf++)
#pragma unroll
                for (int nf = 0; nf < 8; nf++)
                    mma_tf32(acc[mf][nf][0], acc[mf][nf][1],
                             acc[mf][nf][2], acc[mf][nf][3],
                             afr[mf][0], afr[mf][1], afr[mf][2], afr[mf][3],
                             bfr[nf][0], bfr[nf][1]);
        }
    }

    const int row0 = by * 128 + warpM;
    const int col0 = bx * 128 + warpN;
#pragma unroll
    for (int mf = 0; mf < 2; mf++) {
#pragma unroll
        for (int nf = 0; nf < 8; nf++) {
            const int c = col0 + nf * 8 + 2 * tig;
            float bv0 = 0.f, bv1 = 0.f;
            if (bias) { bv0 = bias[c]; bv1 = bias[c + 1]; }
#pragma unroll
            for (int half = 0; half < 2; half++) {
                const int r = row0 + mf * 16 + gid + half * 8;
                float v0 = acc[mf][nf][half * 2 + 0] + bv0;
                float v1 = acc[mf][nf][half * 2 + 1] + bv1;
                if (MODE == 1) {
                    const float2 e = *(const float2*)(extra + (size_t)r * N + c);
                    v0 += e.x; v1 += e.y;
                }
                float2 out = { v0, v1 };
                *(float2*)(C + (size_t)r * N + c) = out;
            }
        }
    }
}

// Mega launch: 7 independent GEMMs. Blocks 0..63: jobs 0-3 (proj, 16 CTAs
// each: 8x * 2y). Blocks 64..831: jobs 4-6 (gates, 256 CTAs each: 8x * 32y).
__global__ void __launch_bounds__(256, 2) mega_gemm(MegaJobs jobs)
{
    extern __shared__ char dynsm[];
    const int id = blockIdx.x;
    int job, bx, by;
    if (id < 64) {
        job = id >> 4;
        const int rem = id & 15;
        bx = rem & 7; by = rem >> 3;
    } else {
        const int t2 = id - 64;
        job = 4 + (t2 >> 8);
        const int rem = t2 & 255;
        bx = rem & 7; by = rem >> 3;
    }
    gemm_core<0>(jobs.A[job], jobs.BT[job], jobs.bias[job], nullptr,
                 jobs.C[job], MM, MM, bx, by, dynsm);
}

// mp2 GEMM (residual epilogue)
__global__ void __launch_bounds__(256, 2) mp2_gemm(GemmJob job)
{
    extern __shared__ char dynsm[];
    gemm_core<1>(job.A, job.BT, job.bias, job.extra, job.C,
                 MM, MM, blockIdx.x, blockIdx.y, dynsm);
}

// ---------------- attention kernel ----------------
__global__ void __launch_bounds__(256) attn_kernel(
    const float* __restrict__ m_state, float* __restrict__ mp_out)
{
    const int bh = blockIdx.x;
    const int b = bh >> 3;
    const int h = bh & 7;
    const int tid = threadIdx.x;

    __shared__ float kv[17][128];
    __shared__ float sc[16][18];

    const float* mbase = m_state + (size_t)b * SS * MM + h * HSZ;
    for (int idx = tid; idx < 16 * 128; idx += 256) {
        int j = idx >> 7, d = idx & 127;
        kv[j][d] = mbase[(size_t)j * MM + d];
    }
    if (tid < 128) kv[16][tid] = g_dense[(size_t)b * MM + h * HSZ + tid];
    __syncthreads();

    const int warp = tid >> 5, lane = tid & 31;
    for (int s = warp; s < 16 * 17; s += 8) {
        const int i = s / 17, j = s % 17;
        float sum = 0.f;
#pragma unroll
        for (int t = 0; t < 4; t++)
            sum += kv[i][lane + t * 32] * kv[j][lane + t * 32];
#pragma unroll
        for (int off = 16; off; off >>= 1)
            sum += __shfl_xor_sync(0xffffffff, sum, off);
        if (lane == 0) sc[i][j] = sum * 0.08838834764831845f;
    }
    __syncthreads();

    if (tid < 16) {
        float mx = -1e30f;
#pragma unroll
        for (int j = 0; j < 17; j++) mx = fmaxf(mx, sc[tid][j]);
        float sum = 0.f;
#pragma unroll
        for (int j = 0; j < 17; j++) {
            float e = expf(sc[tid][j] - mx);
            sc[tid][j] = e;
            sum += e;
        }
        const float inv = 1.f / sum;
#pragma unroll
        for (int j = 0; j < 17; j++) sc[tid][j] *= inv;
    }
    __syncthreads();

    for (int idx = tid; idx < 16 * 128; idx += 256) {
        const int i = idx >> 7, d = idx & 127;
        float a = 0.f;
#pragma unroll
        for (int j = 0; j < 17; j++) a += sc[i][j] * kv[j][d];
        mp_out[((size_t)b * SS + i) * MM + h * HSZ + d] = kv[i][d] + a;
    }
}

// ---------------- final elementwise gating (x-broadcast added here) -------
__device__ __forceinline__ float sigm(float x) { return 1.f / (1.f + expf(-x)); }

__global__ void __launch_bounds__(256) final_kernel(
    const float4* __restrict__ m, const float4* __restrict__ mp2,
    const float4* __restrict__ gf, const float4* __restrict__ gi,
    const float4* __restrict__ go,
    const float4* __restrict__ xf, const float4* __restrict__ xi,
    const float4* __restrict__ xo, float4* __restrict__ out)
{
    const size_t i = (size_t)blockIdx.x * 256 + threadIdx.x;
    const int row  = (int)(i >> 8);          // / (MM/4)
    const int b    = row >> 4;
    const int col4 = (int)(i & 255);
    const size_t xidx = (size_t)b * 256 + col4;

    float4 mv = m[i], p = mp2[i], f = gf[i], ig = gi[i], og = go[i];
    const float4 fx = xf[xidx], ix = xi[xidx], ox = xo[xidx];

    float4 nm, nh;
    nm.x = sigm(mv.x * sigm(f.x + fx.x) + 1.f) + p.x * sigm(sigm(ig.x + ix.x));
    nm.y = sigm(mv.y * sigm(f.y + fx.y) + 1.f) + p.y * sigm(sigm(ig.y + ix.y));
    nm.z = sigm(mv.z * sigm(f.z + fx.z) + 1.f) + p.z * sigm(sigm(ig.z + ix.z));
    nm.w = sigm(mv.w * sigm(f.w + fx.w) + 1.f) + p.w * sigm(sigm(ig.w + ix.w));

    nh.x = tanhf(mv.x) * sigm(sigm(og.x + ox.x));
    nh.y = tanhf(mv.y) * sigm(sigm(og.y + ox.y));
    nh.z = tanhf(mv.z) * sigm(sigm(og.z + ox.z));
    nh.w = tanhf(mv.w) * sigm(sigm(og.w + ox.w));

    out[i] = nm;
    out[(N_ELEM / 4) + i] = nh;
}

// ---------------- launch ----------------
extern "C" void kernel_launch(void* const* d_in, const int* in_sizes, int n_in,
                              void* d_out, int out_size)
{
    const float* inputs  = (const float*)d_in[0];
    const float* h_state = (const float*)d_in[1];
    const float* m_state = (const float*)d_in[2];
    const float* W_emb   = (const float*)d_in[3];
    const float* b_emb   = (const float*)d_in[4];
    const float* W_g     = (const float*)d_in[5];
    const float* b_g     = (const float*)d_in[6];
    const float* W_wf    = (const float*)d_in[7];
    const float* W_wi    = (const float*)d_in[8];
    const float* W_wo    = (const float*)d_in[9];
    const float* W_uf    = (const float*)d_in[10];
    const float* b_uf    = (const float*)d_in[11];
    const float* W_ui    = (const float*)d_in[12];
    const float* b_ui    = (const float*)d_in[13];
    const float* W_uo    = (const float*)d_in[14];
    const float* b_uo    = (const float*)d_in[15];

    float *p_dense, *p_xf, *p_xi, *p_xo, *p_mp, *p_mp2, *p_gf, *p_gi, *p_go, *p_wT;
    cudaGetSymbolAddress((void**)&p_dense, g_dense);
    cudaGetSymbolAddress((void**)&p_xf, g_xf);
    cudaGetSymbolAddress((void**)&p_xi, g_xi);
    cudaGetSymbolAddress((void**)&p_xo, g_xo);
    cudaGetSymbolAddress((void**)&p_mp, g_mp);
    cudaGetSymbolAddress((void**)&p_mp2, g_mp2);
    cudaGetSymbolAddress((void**)&p_gf, g_gf);
    cudaGetSymbolAddress((void**)&p_gi, g_gi);
    cudaGetSymbolAddress((void**)&p_go, g_go);
    cudaGetSymbolAddress((void**)&p_wT, g_wT);

    float* wt[8];
    for (int i = 0; i < 8; i++) wt[i] = p_wT + (size_t)i * MM * MM;

    cudaFuncSetAttribute(mega_gemm, cudaFuncAttributeMaxDynamicSharedMemorySize, GEMM_SMEM);
    cudaFuncSetAttribute(mp2_gemm, cudaFuncAttributeMaxDynamicSharedMemorySize, GEMM_SMEM);

    // 0) transpose all 8 weight matrices: order emb, wf, wi, wo, uf, ui, uo, g
    {
        TPtrs tp;
        tp.src[0] = W_emb; tp.src[1] = W_wf; tp.src[2] = W_wi; tp.src[3] = W_wo;
        tp.src[4] = W_uf;  tp.src[5] = W_ui; tp.src[6] = W_uo; tp.src[7] = W_g;
        for (int i = 0; i < 8; i++) tp.dst[i] = wt[i];
        transpose_k<<<dim3(32, 32, 8), dim3(32, 8)>>>(tp);
    }

    // 1) ALL 7 independent GEMMs in one launch:
    //    jobs 0-3: dense/xf/xi/xo (A=inputs, 16 CTAs each)
    //    jobs 4-6: gate pre-activations WITHOUT x-term (A=h_state, 256 each)
    {
        MegaJobs mj;
        mj.A[0] = inputs;  mj.BT[0] = wt[0]; mj.bias[0] = b_emb;   mj.C[0] = p_dense;
        mj.A[1] = inputs;  mj.BT[1] = wt[1]; mj.bias[1] = nullptr; mj.C[1] = p_xf;
        mj.A[2] = inputs;  mj.BT[2] = wt[2]; mj.bias[2] = nullptr; mj.C[2] = p_xi;
        mj.A[3] = inputs;  mj.BT[3] = wt[3]; mj.bias[3] = nullptr; mj.C[3] = p_xo;
        mj.A[4] = h_state; mj.BT[4] = wt[4]; mj.bias[4] = b_uf;    mj.C[4] = p_gf;
        mj.A[5] = h_state; mj.BT[5] = wt[5]; mj.bias[5] = b_ui;    mj.C[5] = p_gi;
        mj.A[6] = h_state; mj.BT[6] = wt[6]; mj.bias[6] = b_uo;    mj.C[6] = p_go;
        mega_gemm<<<832, 256, GEMM_SMEM>>>(mj);
    }

    // 2) attention -> memory proposal (needs g_dense)
    attn_kernel<<<BB * HH, 256>>>(m_state, p_mp);

    // 3) mp2 = mp @ W_g + b_g + mp
    {
        GemmJob gj = { p_mp, wt[7], b_g, p_mp, p_mp2 };
        mp2_gemm<<<dim3(MM/128, ROWS_L/128), 256, GEMM_SMEM>>>(gj);
    }

    // 4) final gating (adds x-broadcast terms before the sigmoids)
    final_kernel<<<(unsigned)(N_ELEM / 4 / 256), 256>>>(
        (const float4*)m_state, (const float4*)p_mp2,
        (const float4*)p_gf, (const float4*)p_gi, (const float4*)p_go,
        (const float4*)p_xf, (const float4*)p_xi, (const float4*)p_xo,
        (float4*)d_out);
}